// round 1
// baseline (speedup 1.0000x reference)
#include <cuda_runtime.h>
#include <math.h>
#include <stdint.h>

#define NN 50000
#define EE 800000
#define FIN 128
#define DD1 256
#define DD2 64
#define HATT 128

// ---------------- scratch (device globals; no runtime allocation) ----------------
__device__ float g_E  [(size_t)NN * 128];   // edge accumulator (dim<=128)
__device__ float g_acc[(size_t)NN * 128];   // node accumulator (dim<=128)
__device__ float g_C1 [(size_t)NN * 256];   // conv1 output
__device__ float g_G  [(size_t)NN * 64];    // conv2 pre-propagation GEMM out
__device__ float g_x1 [4 * (size_t)NN * 64];
__device__ float g_x2 [4 * (size_t)NN * 64];
__device__ float g_dinv[NN];
__device__ float g_binv[NN];
__device__ float g_wsum[8];
__device__ float g_beta[8];

// ---------------- helpers ----------------
__device__ __forceinline__ void red4(float* a, float4 v) {
    asm volatile("red.global.add.v4.f32 [%0], {%1,%2,%3,%4};"
                 :: "l"(a), "f"(v.x), "f"(v.y), "f"(v.z), "f"(v.w) : "memory");
}

__global__ void fill0_kernel(float* __restrict__ p, int n4) {
    int t = blockIdx.x * blockDim.x + threadIdx.x;
    if (t < n4) reinterpret_cast<float4*>(p)[t] = make_float4(0.f, 0.f, 0.f, 0.f);
}

__global__ void deg_kernel(const int* __restrict__ ei, float* dn, float* de) {
    int t = blockIdx.x * blockDim.x + threadIdx.x;
    if (t < EE) {
        atomicAdd(dn + ei[t], 1.0f);          // node degree
        atomicAdd(de + ei[t + EE], 1.0f);     // hyperedge degree
    }
}

__global__ void invert_kernel(float* __restrict__ d, int n) {
    int t = blockIdx.x * blockDim.x + threadIdx.x;
    if (t < n) { float v = d[t]; d[t] = (v > 0.f) ? (1.0f / v) : 0.f; }
}

// gather src[gidx[e]] (optionally scaled by scal[gidx[e]]) and reduce into dst[sidx[e]]
template<int LOG4, bool SCALE>
__global__ __launch_bounds__(256) void prop_kernel(
    const float* __restrict__ src, const int* __restrict__ gidx,
    const int* __restrict__ sidx, const float* __restrict__ scal,
    float* __restrict__ dst)
{
    int t = blockIdx.x * blockDim.x + threadIdx.x;
    int e = t >> LOG4;
    int c = t & ((1 << LOG4) - 1);
    if (e < EE) {
        int g = __ldg(gidx + e);
        int s = __ldg(sidx + e);
        float4 v = __ldg(reinterpret_cast<const float4*>(src) + (((size_t)g) << LOG4) + c);
        if (SCALE) {
            float b = __ldg(scal + g);
            v.x *= b; v.y *= b; v.z *= b; v.w *= b;
        }
        red4(reinterpret_cast<float*>(
                 reinterpret_cast<float4*>(dst) + (((size_t)s) << LOG4) + c), v);
    }
}

// ---------------- GEMM: C[M,Nn] = A[M,K] @ B[K,Nn], optional rowscale+bias+relu ----
template<bool ROWSCALE, bool BIASRELU>
__global__ __launch_bounds__(256) void gemm64_kernel(
    const float* __restrict__ A, const float* __restrict__ B,
    const float* __restrict__ bias, const float* __restrict__ rs,
    float* __restrict__ C, int M, int Nn, int K)
{
    const int BM = 64, BN = 64, BK = 16;
    __shared__ __align__(16) float As[BK][BM + 4];
    __shared__ __align__(16) float Bs[BK][BN + 4];
    int tid = threadIdx.x;
    int bm = blockIdx.x * BM, bn = blockIdx.y * BN;
    int tx = tid & 15, ty = tid >> 4;
    int arow = tid >> 2,  ac4 = (tid & 3) << 2;
    int brow = tid >> 4,  bc4 = (tid & 15) << 2;
    float acc[4][4] = {};
    for (int k0 = 0; k0 < K; k0 += BK) {
        float4 av = make_float4(0.f, 0.f, 0.f, 0.f);
        if (bm + arow < M)
            av = *reinterpret_cast<const float4*>(A + (size_t)(bm + arow) * K + k0 + ac4);
        As[ac4 + 0][arow] = av.x; As[ac4 + 1][arow] = av.y;
        As[ac4 + 2][arow] = av.z; As[ac4 + 3][arow] = av.w;
        float4 bv = *reinterpret_cast<const float4*>(B + (size_t)(k0 + brow) * Nn + bn + bc4);
        *reinterpret_cast<float4*>(&Bs[brow][bc4]) = bv;
        __syncthreads();
#pragma unroll
        for (int kk = 0; kk < BK; kk++) {
            float4 a4 = *reinterpret_cast<float4*>(&As[kk][ty << 2]);
            float4 b4 = *reinterpret_cast<float4*>(&Bs[kk][tx << 2]);
            float aa[4] = {a4.x, a4.y, a4.z, a4.w};
            float bb[4] = {b4.x, b4.y, b4.z, b4.w};
#pragma unroll
            for (int i = 0; i < 4; i++)
#pragma unroll
                for (int j = 0; j < 4; j++)
                    acc[i][j] = fmaf(aa[i], bb[j], acc[i][j]);
        }
        __syncthreads();
    }
#pragma unroll
    for (int i = 0; i < 4; i++) {
        int m = bm + (ty << 2) + i;
        if (m < M) {
            float sc = ROWSCALE ? rs[m] : 1.0f;
#pragma unroll
            for (int j = 0; j < 4; j++) {
                int nc = bn + (tx << 2) + j;
                float v = acc[i][j] * sc;
                if (BIASRELU) v = fmaxf(v + bias[nc], 0.f);
                C[(size_t)m * Nn + nc] = v;
            }
        }
    }
}

// x1 = relu(dinv[n]*acc + b2[c]),  dim 64
__global__ void bias_relu_kernel(const float* __restrict__ acc, const float* __restrict__ dinv,
                                 const float* __restrict__ bias, float* __restrict__ out)
{
    int t = blockIdx.x * blockDim.x + threadIdx.x;
    if (t < NN * 64) {
        int n = t >> 6, c = t & 63;
        out[t] = fmaxf(fmaf(dinv[n], acc[t], bias[c]), 0.f);
    }
}

// hyperedge embedding: mean of gathered node rows (padding index 0 -> zero row)
__global__ void hye_kernel(const float* __restrict__ x1, const int* __restrict__ hnode,
                           const float* __restrict__ hlen, float* __restrict__ x2)
{
    int n = blockIdx.x * blockDim.y + threadIdx.y;
    if (n >= NN) return;
    int c = threadIdx.x;   // 0..63
    float s = 0.f;
#pragma unroll
    for (int l = 0; l < 16; l++) {
        int j = __ldg(hnode + (size_t)n * 16 + l);
        if (j > 0) s += __ldg(x1 + (size_t)(j - 1) * 64 + c);
    }
    x2[(size_t)n * 64 + c] = s / (__ldg(hlen + n) + 1e-15f);
}

// fusion-attention scores: wsum[s] = sum_n (tanh(z_ns @ W1 + b1) @ W2)
__global__ __launch_bounds__(256) void attn_kernel(
    const float* __restrict__ z0, const float* __restrict__ z1,
    const float* __restrict__ z2, const float* __restrict__ z3,
    const float* __restrict__ W1, const float* __restrict__ b1,
    const float* __restrict__ W2, float* __restrict__ wsum)
{
    __shared__ __align__(16) float sW1[64 * 128];
    __shared__ __align__(16) float sb1[128];
    __shared__ __align__(16) float sW2[128];
    for (int i = threadIdx.x; i < 64 * 128; i += 256) sW1[i] = W1[i];
    if (threadIdx.x < 128) { sb1[threadIdx.x] = b1[threadIdx.x]; sW2[threadIdx.x] = W2[threadIdx.x]; }
    __syncthreads();
    const float* zs[4] = {z0, z1, z2, z3};
    int warp = threadIdx.x >> 5, lane = threadIdx.x & 31;
    float accs[4] = {0.f, 0.f, 0.f, 0.f};
    float4 hb = *reinterpret_cast<const float4*>(&sb1[lane << 2]);
    float4 w2 = *reinterpret_cast<const float4*>(&sW2[lane << 2]);
    for (int n = blockIdx.x * 8 + warp; n < NN; n += gridDim.x * 8) {
#pragma unroll
        for (int s = 0; s < 4; s++) {
            const float* v = zs[s] + (size_t)n * 64;
            float h0 = hb.x, h1 = hb.y, h2 = hb.z, h3 = hb.w;
#pragma unroll
            for (int k = 0; k < 64; k++) {
                float vk = __ldg(v + k);
                float4 w = *reinterpret_cast<const float4*>(&sW1[k * 128 + (lane << 2)]);
                h0 = fmaf(vk, w.x, h0); h1 = fmaf(vk, w.y, h1);
                h2 = fmaf(vk, w.z, h2); h3 = fmaf(vk, w.w, h3);
            }
            float r = tanhf(h0) * w2.x + tanhf(h1) * w2.y + tanhf(h2) * w2.z + tanhf(h3) * w2.w;
#pragma unroll
            for (int o = 16; o; o >>= 1) r += __shfl_xor_sync(0xffffffffu, r, o);
            if (lane == 0) accs[s] += r;
        }
    }
    if (lane == 0) {
#pragma unroll
        for (int s = 0; s < 4; s++) atomicAdd(wsum + s, accs[s]);
    }
}

__global__ void beta_kernel(const float* __restrict__ wsum, float* __restrict__ beta) {
    if (threadIdx.x == 0 && blockIdx.x == 0) {
        for (int h = 0; h < 2; h++) {
            float v[4], m = -1e30f;
            for (int s = 0; s < 4; s++) { v[s] = wsum[h * 4 + s] / (float)NN; if (v[s] > m) m = v[s]; }
            float sum = 0.f;
            for (int s = 0; s < 4; s++) { v[s] = expf(v[s] - m); sum += v[s]; }
            for (int s = 0; s < 4; s++) beta[h * 4 + s] = v[s] / sum;
        }
    }
}

__global__ void combine_kernel(const float* __restrict__ z0, const float* __restrict__ z1,
                               const float* __restrict__ z2, const float* __restrict__ z3,
                               const float* __restrict__ beta, float* __restrict__ out)
{
    int t = blockIdx.x * blockDim.x + threadIdx.x;
    if (t < NN * 16) {
        float b0 = __ldg(beta + 0), b1 = __ldg(beta + 1), b2 = __ldg(beta + 2), b3 = __ldg(beta + 3);
        float4 a = __ldg(reinterpret_cast<const float4*>(z0) + t);
        float4 b = __ldg(reinterpret_cast<const float4*>(z1) + t);
        float4 c = __ldg(reinterpret_cast<const float4*>(z2) + t);
        float4 d = __ldg(reinterpret_cast<const float4*>(z3) + t);
        float4 o;
        o.x = b0 * a.x + b1 * b.x + b2 * c.x + b3 * d.x;
        o.y = b0 * a.y + b1 * b.y + b2 * c.y + b3 * d.y;
        o.z = b0 * a.z + b1 * b.z + b2 * c.z + b3 * d.z;
        o.w = b0 * a.w + b1 * b.w + b2 * c.w + b3 * d.w;
        reinterpret_cast<float4*>(out)[t] = o;
    }
}

// ---------------- host launcher ----------------
extern "C" void kernel_launch(void* const* d_in, const int* in_sizes, int n_in,
                              void* d_out, int out_size)
{
    // Classify inputs by element count + order of appearance (robust to
    // per-graph vs per-type metadata ordering; both preserve within-class order).
    int xi[4], eii[4], hni[4], hli[4];
    int nx = 0, ne = 0, nh = 0, nl = 0;
    int iW1 = -1, ib1 = -1, iW2 = -1, ib2 = -1;
    int i8192[2]; int n8 = 0;
    int i128[4];  int n128 = 0;
    for (int i = 0; i < n_in; i++) {
        switch (in_sizes[i]) {
            case NN * FIN:   if (nx < 4) xi[nx++] = i; break;     // 6,400,000
            case 2 * EE:     if (ne < 4) eii[ne++] = i; break;    // 1,600,000
            case NN * 16:    if (nh < 4) hni[nh++] = i; break;    // 800,000
            case NN:         if (nl < 4) hli[nl++] = i; break;    // 50,000
            case FIN * DD1:  iW1 = i; break;                      // 32,768
            case DD1:        ib1 = i; break;                      // 256
            case DD1 * DD2:  iW2 = i; break;                      // 16,384
            case DD2:        ib2 = i; break;                      // 64
            case DD2 * HATT: if (n8 < 2) i8192[n8++] = i; break;  // 8,192
            case HATT:       if (n128 < 4) i128[n128++] = i; break; // 128
            default: break;
        }
    }
    const float* X[4]; const int* EIN[4]; const int* EIE[4];
    const int* HN[4]; const float* HL[4];
    for (int i = 0; i < 4; i++) {
        X[i]   = (const float*)d_in[xi[i]];
        EIN[i] = (const int*)d_in[eii[i]];        // node indices  = ei[0]
        EIE[i] = (const int*)d_in[eii[i]] + EE;   // edge indices  = ei[1]
        HN[i]  = (const int*)d_in[hni[i]];
        HL[i]  = (const float*)d_in[hli[i]];
    }
    const float* W1 = (const float*)d_in[iW1];
    const float* B1 = (const float*)d_in[ib1];
    const float* W2 = (const float*)d_in[iW2];
    const float* B2 = (const float*)d_in[ib2];
    const float* acW1 = (const float*)d_in[i8192[0]];
    const float* amW1 = (const float*)d_in[i8192[1]];
    const float* acB1 = (const float*)d_in[i128[0]];
    const float* acW2 = (const float*)d_in[i128[1]];
    const float* amB1 = (const float*)d_in[i128[2]];
    const float* amW2 = (const float*)d_in[i128[3]];

    float *E_, *ACC, *C1, *G, *X1, *X2, *DINV, *BINV, *WSUM, *BETA;
    cudaGetSymbolAddress((void**)&E_,   g_E);
    cudaGetSymbolAddress((void**)&ACC,  g_acc);
    cudaGetSymbolAddress((void**)&C1,   g_C1);
    cudaGetSymbolAddress((void**)&G,    g_G);
    cudaGetSymbolAddress((void**)&X1,   g_x1);
    cudaGetSymbolAddress((void**)&X2,   g_x2);
    cudaGetSymbolAddress((void**)&DINV, g_dinv);
    cudaGetSymbolAddress((void**)&BINV, g_binv);
    cudaGetSymbolAddress((void**)&WSUM, g_wsum);
    cudaGetSymbolAddress((void**)&BETA, g_beta);

    const size_t S = (size_t)NN * 64;
    const int TB = 256;
    auto gb = [](long n, int tb) { return (int)((n + tb - 1) / tb); };

    for (int i = 0; i < 4; i++) {
        // degrees -> inverse degrees
        fill0_kernel<<<gb(NN / 4, TB), TB>>>(DINV, NN / 4);
        fill0_kernel<<<gb(NN / 4, TB), TB>>>(BINV, NN / 4);
        deg_kernel<<<gb(EE, TB), TB>>>(EIN[i] /* [2,E] base */, DINV, BINV);
        invert_kernel<<<gb(NN, TB), TB>>>(DINV, NN);
        invert_kernel<<<gb(NN, TB), TB>>>(BINV, NN);

        // conv1 propagation in 128 dims (GEMM commuted past the propagation)
        fill0_kernel<<<gb((long)NN * 32, TB), TB>>>(E_, NN * 32);
        prop_kernel<5, false><<<gb((long)EE * 32, TB), TB>>>(X[i], EIN[i], EIE[i], nullptr, E_);
        fill0_kernel<<<gb((long)NN * 32, TB), TB>>>(ACC, NN * 32);
        prop_kernel<5, true><<<gb((long)EE * 32, TB), TB>>>(E_, EIE[i], EIN[i], BINV, ACC);

        // conv1 GEMM with fused D^-1 rowscale + bias + relu
        gemm64_kernel<true, true><<<dim3(782, 4), TB>>>(ACC, W1, B1, DINV, C1, NN, DD1, FIN);
        // conv2 GEMM (to 64 dims) then propagate in 64 dims
        gemm64_kernel<false, false><<<dim3(782, 1), TB>>>(C1, W2, nullptr, nullptr, G, NN, DD2, DD1);

        fill0_kernel<<<gb((long)NN * 16, TB), TB>>>(E_, NN * 16);
        prop_kernel<4, false><<<gb((long)EE * 16, TB), TB>>>(G, EIN[i], EIE[i], nullptr, E_);
        fill0_kernel<<<gb((long)NN * 16, TB), TB>>>(ACC, NN * 16);
        prop_kernel<4, true><<<gb((long)EE * 16, TB), TB>>>(E_, EIE[i], EIN[i], BINV, ACC);

        bias_relu_kernel<<<gb((long)NN * 64, TB), TB>>>(ACC, DINV, B2, X1 + (size_t)i * S);
        hye_kernel<<<gb(NN, 8), dim3(64, 8)>>>(X1 + (size_t)i * S, HN[i], HL[i], X2 + (size_t)i * S);
    }

    // fusion attention
    fill0_kernel<<<1, TB>>>(WSUM, 2);
    // head c slots: (x1_mc, x2_cm, x1_cc, x2_cc)
    attn_kernel<<<592, TB>>>(X1 + 1 * S, X2 + 0 * S, X1 + 2 * S, X2 + 2 * S,
                             acW1, acB1, acW2, WSUM);
    // head m slots: (x1_cm, x2_mc, x1_mm, x2_mm)
    attn_kernel<<<592, TB>>>(X1 + 0 * S, X2 + 1 * S, X1 + 3 * S, X2 + 3 * S,
                             amW1, amB1, amW2, WSUM + 4);
    beta_kernel<<<1, 32>>>(WSUM, BETA);

    float* out = (float*)d_out;
    combine_kernel<<<gb((long)NN * 16, TB), TB>>>(X1 + 1 * S, X2 + 0 * S, X1 + 2 * S, X2 + 2 * S,
                                                  BETA, out);
    combine_kernel<<<gb((long)NN * 16, TB), TB>>>(X1 + 0 * S, X2 + 1 * S, X1 + 3 * S, X2 + 3 * S,
                                                  BETA + 4, out + S);
}

// round 2
// speedup vs baseline: 1.1166x; 1.1166x over previous
#include <cuda_runtime.h>
#include <math.h>
#include <stdint.h>

#define NN 50000
#define EE 800000
#define FIN 128
#define DD1 256
#define DD2 64
#define HATT 128

// ---------------- scratch (device globals; no runtime allocation) ----------------
__device__ float g_E  [(size_t)NN * 128];   // edge accumulator (dim<=128)
__device__ float g_acc[(size_t)NN * 128];   // node accumulator (dim<=128)
__device__ float g_C1 [(size_t)NN * 256];   // conv1 output
__device__ float g_G  [(size_t)NN * 64];    // conv2 pre-propagation GEMM out
__device__ float g_x1 [4 * (size_t)NN * 64];
__device__ float g_x2 [4 * (size_t)NN * 64];
__device__ float g_dinv[NN];
__device__ float g_binv[NN];
__device__ float g_wsum[8];
__device__ float g_beta[8];
// CSR scratch (rebuilt per graph)
__device__ int g_degn[NN];
__device__ int g_dege[NN];
__device__ int g_startn[NN];
__device__ int g_starte[NN];
__device__ int g_curn[NN];
__device__ int g_cure[NN];
__device__ int g_adjn[EE];   // edge ids grouped by node
__device__ int g_adje[EE];   // node ids grouped by edge
__device__ int g_cnt[2];

// ---------------- utility kernels ----------------
__global__ void fill0_kernel(float* __restrict__ p, int n4) {
    int t = blockIdx.x * blockDim.x + threadIdx.x;
    if (t < n4) reinterpret_cast<float4*>(p)[t] = make_float4(0.f, 0.f, 0.f, 0.f);
}

__global__ void deg_kernel(const int* __restrict__ ei, int* dn, int* de) {
    int t = blockIdx.x * blockDim.x + threadIdx.x;
    if (t < EE) {
        atomicAdd(dn + __ldg(ei + t), 1);          // node degree
        atomicAdd(de + __ldg(ei + t + EE), 1);     // hyperedge degree
    }
}

// allocate disjoint CSR regions via warp-aggregated atomics; also inverse degrees
__global__ void alloc_kernel(const int* __restrict__ degn, const int* __restrict__ dege,
                             int* __restrict__ startn, int* __restrict__ starte,
                             float* __restrict__ dinv, float* __restrict__ binv,
                             int* __restrict__ cnt)
{
    int t = blockIdx.x * blockDim.x + threadIdx.x;
    int lane = threadIdx.x & 31;
    int dn = (t < NN) ? __ldg(degn + t) : 0;
    int de = (t < NN) ? __ldg(dege + t) : 0;
    // inclusive warp scans
    int sn = dn, se = de;
#pragma unroll
    for (int o = 1; o < 32; o <<= 1) {
        int vn = __shfl_up_sync(0xffffffffu, sn, o);
        int ve = __shfl_up_sync(0xffffffffu, se, o);
        if (lane >= o) { sn += vn; se += ve; }
    }
    int bn = 0, be = 0;
    if (lane == 31) {
        bn = atomicAdd(cnt + 0, sn);
        be = atomicAdd(cnt + 1, se);
    }
    bn = __shfl_sync(0xffffffffu, bn, 31);
    be = __shfl_sync(0xffffffffu, be, 31);
    if (t < NN) {
        startn[t] = bn + sn - dn;
        starte[t] = be + se - de;
        dinv[t] = dn > 0 ? (1.0f / (float)dn) : 0.f;
        binv[t] = de > 0 ? (1.0f / (float)de) : 0.f;
    }
}

__global__ void scatter_kernel(const int* __restrict__ ei,
                               const int* __restrict__ startn, const int* __restrict__ starte,
                               int* __restrict__ curn, int* __restrict__ cure,
                               int* __restrict__ adjn, int* __restrict__ adje)
{
    int e = blockIdx.x * blockDim.x + threadIdx.x;
    if (e < EE) {
        int v = __ldg(ei + e);
        int h = __ldg(ei + e + EE);
        int p = atomicAdd(cure + h, 1);
        adje[__ldg(starte + h) + p] = v;
        int q = atomicAdd(curn + v, 1);
        adjn[__ldg(startn + v) + q] = h;
    }
}

// segment-sum gather: dst[r] = (SCALE? scal[r]:1) * sum_{j in adj[start[r]..]} src[j]
template<int DIM, bool SCALE>
__global__ __launch_bounds__(256) void seg_gather_kernel(
    const float* __restrict__ src, const int* __restrict__ start,
    const int* __restrict__ deg, const int* __restrict__ adj,
    const float* __restrict__ scal, float* __restrict__ dst)
{
    int warp = (blockIdx.x * blockDim.x + threadIdx.x) >> 5;
    int lane = threadIdx.x & 31;
    if (warp >= NN) return;
    int s = __ldg(start + warp);
    int d = __ldg(deg + warp);
    if (DIM == 128) {
        const float4* S = reinterpret_cast<const float4*>(src);
        float4 a = make_float4(0.f, 0.f, 0.f, 0.f);
        int k = 0;
        for (; k + 4 <= d; k += 4) {
            int j0 = __ldg(adj + s + k + 0), j1 = __ldg(adj + s + k + 1);
            int j2 = __ldg(adj + s + k + 2), j3 = __ldg(adj + s + k + 3);
            float4 v0 = __ldg(S + ((size_t)j0 << 5) + lane);
            float4 v1 = __ldg(S + ((size_t)j1 << 5) + lane);
            float4 v2 = __ldg(S + ((size_t)j2 << 5) + lane);
            float4 v3 = __ldg(S + ((size_t)j3 << 5) + lane);
            a.x += (v0.x + v1.x) + (v2.x + v3.x);
            a.y += (v0.y + v1.y) + (v2.y + v3.y);
            a.z += (v0.z + v1.z) + (v2.z + v3.z);
            a.w += (v0.w + v1.w) + (v2.w + v3.w);
        }
        for (; k < d; k++) {
            int j = __ldg(adj + s + k);
            float4 v = __ldg(S + ((size_t)j << 5) + lane);
            a.x += v.x; a.y += v.y; a.z += v.z; a.w += v.w;
        }
        if (SCALE) { float b = __ldg(scal + warp); a.x *= b; a.y *= b; a.z *= b; a.w *= b; }
        reinterpret_cast<float4*>(dst)[((size_t)warp << 5) + lane] = a;
    } else {   // DIM == 64
        const float2* S = reinterpret_cast<const float2*>(src);
        float2 a = make_float2(0.f, 0.f);
        int k = 0;
        for (; k + 4 <= d; k += 4) {
            int j0 = __ldg(adj + s + k + 0), j1 = __ldg(adj + s + k + 1);
            int j2 = __ldg(adj + s + k + 2), j3 = __ldg(adj + s + k + 3);
            float2 v0 = __ldg(S + ((size_t)j0 << 5) + lane);
            float2 v1 = __ldg(S + ((size_t)j1 << 5) + lane);
            float2 v2 = __ldg(S + ((size_t)j2 << 5) + lane);
            float2 v3 = __ldg(S + ((size_t)j3 << 5) + lane);
            a.x += (v0.x + v1.x) + (v2.x + v3.x);
            a.y += (v0.y + v1.y) + (v2.y + v3.y);
        }
        for (; k < d; k++) {
            int j = __ldg(adj + s + k);
            float2 v = __ldg(S + ((size_t)j << 5) + lane);
            a.x += v.x; a.y += v.y;
        }
        if (SCALE) { float b = __ldg(scal + warp); a.x *= b; a.y *= b; }
        reinterpret_cast<float2*>(dst)[((size_t)warp << 5) + lane] = a;
    }
}

// ---------------- GEMM: C[M,Nn] = A[M,K] @ B[K,Nn], optional rowscale+bias+relu ----
template<bool ROWSCALE, bool BIASRELU>
__global__ __launch_bounds__(256) void gemm64_kernel(
    const float* __restrict__ A, const float* __restrict__ B,
    const float* __restrict__ bias, const float* __restrict__ rs,
    float* __restrict__ C, int M, int Nn, int K)
{
    const int BM = 64, BN = 64, BK = 16;
    __shared__ __align__(16) float As[BK][BM + 4];
    __shared__ __align__(16) float Bs[BK][BN + 4];
    int tid = threadIdx.x;
    int bm = blockIdx.x * BM, bn = blockIdx.y * BN;
    int tx = tid & 15, ty = tid >> 4;
    int arow = tid >> 2,  ac4 = (tid & 3) << 2;
    int brow = tid >> 4,  bc4 = (tid & 15) << 2;
    float acc[4][4] = {};
    for (int k0 = 0; k0 < K; k0 += BK) {
        float4 av = make_float4(0.f, 0.f, 0.f, 0.f);
        if (bm + arow < M)
            av = *reinterpret_cast<const float4*>(A + (size_t)(bm + arow) * K + k0 + ac4);
        As[ac4 + 0][arow] = av.x; As[ac4 + 1][arow] = av.y;
        As[ac4 + 2][arow] = av.z; As[ac4 + 3][arow] = av.w;
        float4 bv = *reinterpret_cast<const float4*>(B + (size_t)(k0 + brow) * Nn + bn + bc4);
        *reinterpret_cast<float4*>(&Bs[brow][bc4]) = bv;
        __syncthreads();
#pragma unroll
        for (int kk = 0; kk < BK; kk++) {
            float4 a4 = *reinterpret_cast<float4*>(&As[kk][ty << 2]);
            float4 b4 = *reinterpret_cast<float4*>(&Bs[kk][tx << 2]);
            float aa[4] = {a4.x, a4.y, a4.z, a4.w};
            float bb[4] = {b4.x, b4.y, b4.z, b4.w};
#pragma unroll
            for (int i = 0; i < 4; i++)
#pragma unroll
                for (int j = 0; j < 4; j++)
                    acc[i][j] = fmaf(aa[i], bb[j], acc[i][j]);
        }
        __syncthreads();
    }
#pragma unroll
    for (int i = 0; i < 4; i++) {
        int m = bm + (ty << 2) + i;
        if (m < M) {
            float sc = ROWSCALE ? rs[m] : 1.0f;
#pragma unroll
            for (int j = 0; j < 4; j++) {
                int nc = bn + (tx << 2) + j;
                float v = acc[i][j] * sc;
                if (BIASRELU) v = fmaxf(v + bias[nc], 0.f);
                C[(size_t)m * Nn + nc] = v;
            }
        }
    }
}

// x1 = relu(dinv[n]*acc + b2[c]),  dim 64
__global__ void bias_relu_kernel(const float* __restrict__ acc, const float* __restrict__ dinv,
                                 const float* __restrict__ bias, float* __restrict__ out)
{
    int t = blockIdx.x * blockDim.x + threadIdx.x;
    if (t < NN * 64) {
        int n = t >> 6, c = t & 63;
        out[t] = fmaxf(fmaf(__ldg(dinv + n), acc[t], __ldg(bias + c)), 0.f);
    }
}

// hyperedge embedding: mean of gathered node rows (padding index 0 -> zero row)
__global__ void hye_kernel(const float* __restrict__ x1, const int* __restrict__ hnode,
                           const float* __restrict__ hlen, float* __restrict__ x2)
{
    int n = blockIdx.x * blockDim.y + threadIdx.y;
    if (n >= NN) return;
    int c = threadIdx.x;   // 0..63
    float s = 0.f;
#pragma unroll
    for (int l = 0; l < 16; l++) {
        int j = __ldg(hnode + (size_t)n * 16 + l);
        if (j > 0) s += __ldg(x1 + (size_t)(j - 1) * 64 + c);
    }
    x2[(size_t)n * 64 + c] = s / (__ldg(hlen + n) + 1e-15f);
}

// fusion-attention scores: wsum[s] = sum_n (tanh(z_ns @ W1 + b1) @ W2)
__global__ __launch_bounds__(256) void attn_kernel(
    const float* __restrict__ z0, const float* __restrict__ z1,
    const float* __restrict__ z2, const float* __restrict__ z3,
    const float* __restrict__ W1, const float* __restrict__ b1,
    const float* __restrict__ W2, float* __restrict__ wsum)
{
    __shared__ __align__(16) float sW1[64 * 128];
    __shared__ __align__(16) float sb1[128];
    __shared__ __align__(16) float sW2[128];
    for (int i = threadIdx.x; i < 64 * 128; i += 256) sW1[i] = W1[i];
    if (threadIdx.x < 128) { sb1[threadIdx.x] = b1[threadIdx.x]; sW2[threadIdx.x] = W2[threadIdx.x]; }
    __syncthreads();
    const float* zs[4] = {z0, z1, z2, z3};
    int warp = threadIdx.x >> 5, lane = threadIdx.x & 31;
    float accs[4] = {0.f, 0.f, 0.f, 0.f};
    float4 hb = *reinterpret_cast<const float4*>(&sb1[lane << 2]);
    float4 w2 = *reinterpret_cast<const float4*>(&sW2[lane << 2]);
    for (int n = blockIdx.x * 8 + warp; n < NN; n += gridDim.x * 8) {
#pragma unroll
        for (int s = 0; s < 4; s++) {
            const float* v = zs[s] + (size_t)n * 64;
            float h0 = hb.x, h1 = hb.y, h2 = hb.z, h3 = hb.w;
#pragma unroll
            for (int k = 0; k < 64; k++) {
                float vk = __ldg(v + k);
                float4 w = *reinterpret_cast<const float4*>(&sW1[k * 128 + (lane << 2)]);
                h0 = fmaf(vk, w.x, h0); h1 = fmaf(vk, w.y, h1);
                h2 = fmaf(vk, w.z, h2); h3 = fmaf(vk, w.w, h3);
            }
            float r = tanhf(h0) * w2.x + tanhf(h1) * w2.y + tanhf(h2) * w2.z + tanhf(h3) * w2.w;
#pragma unroll
            for (int o = 16; o; o >>= 1) r += __shfl_xor_sync(0xffffffffu, r, o);
            if (lane == 0) accs[s] += r;
        }
    }
    if (lane == 0) {
#pragma unroll
        for (int s = 0; s < 4; s++) atomicAdd(wsum + s, accs[s]);
    }
}

__global__ void beta_kernel(const float* __restrict__ wsum, float* __restrict__ beta) {
    if (threadIdx.x == 0 && blockIdx.x == 0) {
        for (int h = 0; h < 2; h++) {
            float v[4], m = -1e30f;
            for (int s = 0; s < 4; s++) { v[s] = wsum[h * 4 + s] / (float)NN; if (v[s] > m) m = v[s]; }
            float sum = 0.f;
            for (int s = 0; s < 4; s++) { v[s] = expf(v[s] - m); sum += v[s]; }
            for (int s = 0; s < 4; s++) beta[h * 4 + s] = v[s] / sum;
        }
    }
}

__global__ void combine_kernel(const float* __restrict__ z0, const float* __restrict__ z1,
                               const float* __restrict__ z2, const float* __restrict__ z3,
                               const float* __restrict__ beta, float* __restrict__ out)
{
    int t = blockIdx.x * blockDim.x + threadIdx.x;
    if (t < NN * 16) {
        float b0 = __ldg(beta + 0), b1 = __ldg(beta + 1), b2 = __ldg(beta + 2), b3 = __ldg(beta + 3);
        float4 a = __ldg(reinterpret_cast<const float4*>(z0) + t);
        float4 b = __ldg(reinterpret_cast<const float4*>(z1) + t);
        float4 c = __ldg(reinterpret_cast<const float4*>(z2) + t);
        float4 d = __ldg(reinterpret_cast<const float4*>(z3) + t);
        float4 o;
        o.x = b0 * a.x + b1 * b.x + b2 * c.x + b3 * d.x;
        o.y = b0 * a.y + b1 * b.y + b2 * c.y + b3 * d.y;
        o.z = b0 * a.z + b1 * b.z + b2 * c.z + b3 * d.z;
        o.w = b0 * a.w + b1 * b.w + b2 * c.w + b3 * d.w;
        reinterpret_cast<float4*>(out)[t] = o;
    }
}

// ---------------- host launcher ----------------
extern "C" void kernel_launch(void* const* d_in, const int* in_sizes, int n_in,
                              void* d_out, int out_size)
{
    int xi[4], eii[4], hni[4], hli[4];
    int nx = 0, ne = 0, nh = 0, nl = 0;
    int iW1 = -1, ib1 = -1, iW2 = -1, ib2 = -1;
    int i8192[2]; int n8 = 0;
    int i128[4];  int n128 = 0;
    for (int i = 0; i < n_in; i++) {
        switch (in_sizes[i]) {
            case NN * FIN:   if (nx < 4) xi[nx++] = i; break;
            case 2 * EE:     if (ne < 4) eii[ne++] = i; break;
            case NN * 16:    if (nh < 4) hni[nh++] = i; break;
            case NN:         if (nl < 4) hli[nl++] = i; break;
            case FIN * DD1:  iW1 = i; break;
            case DD1:        ib1 = i; break;
            case DD1 * DD2:  iW2 = i; break;
            case DD2:        ib2 = i; break;
            case DD2 * HATT: if (n8 < 2) i8192[n8++] = i; break;
            case HATT:       if (n128 < 4) i128[n128++] = i; break;
            default: break;
        }
    }
    const float* X[4]; const int* EI[4];
    const int* HN[4]; const float* HL[4];
    for (int i = 0; i < 4; i++) {
        X[i]  = (const float*)d_in[xi[i]];
        EI[i] = (const int*)d_in[eii[i]];
        HN[i] = (const int*)d_in[hni[i]];
        HL[i] = (const float*)d_in[hli[i]];
    }
    const float* W1 = (const float*)d_in[iW1];
    const float* B1 = (const float*)d_in[ib1];
    const float* W2 = (const float*)d_in[iW2];
    const float* B2 = (const float*)d_in[ib2];
    const float* acW1 = (const float*)d_in[i8192[0]];
    const float* amW1 = (const float*)d_in[i8192[1]];
    const float* acB1 = (const float*)d_in[i128[0]];
    const float* acW2 = (const float*)d_in[i128[1]];
    const float* amB1 = (const float*)d_in[i128[2]];
    const float* amW2 = (const float*)d_in[i128[3]];

    float *E_, *ACC, *C1, *G, *X1, *X2, *DINV, *BINV, *WSUM, *BETA;
    int *DEGN, *DEGE, *STN, *STE, *CURN, *CURE, *ADJN, *ADJE, *CNT;
    cudaGetSymbolAddress((void**)&E_,   g_E);
    cudaGetSymbolAddress((void**)&ACC,  g_acc);
    cudaGetSymbolAddress((void**)&C1,   g_C1);
    cudaGetSymbolAddress((void**)&G,    g_G);
    cudaGetSymbolAddress((void**)&X1,   g_x1);
    cudaGetSymbolAddress((void**)&X2,   g_x2);
    cudaGetSymbolAddress((void**)&DINV, g_dinv);
    cudaGetSymbolAddress((void**)&BINV, g_binv);
    cudaGetSymbolAddress((void**)&WSUM, g_wsum);
    cudaGetSymbolAddress((void**)&BETA, g_beta);
    cudaGetSymbolAddress((void**)&DEGN, g_degn);
    cudaGetSymbolAddress((void**)&DEGE, g_dege);
    cudaGetSymbolAddress((void**)&STN,  g_startn);
    cudaGetSymbolAddress((void**)&STE,  g_starte);
    cudaGetSymbolAddress((void**)&CURN, g_curn);
    cudaGetSymbolAddress((void**)&CURE, g_cure);
    cudaGetSymbolAddress((void**)&ADJN, g_adjn);
    cudaGetSymbolAddress((void**)&ADJE, g_adje);
    cudaGetSymbolAddress((void**)&CNT,  g_cnt);

    const size_t S = (size_t)NN * 64;
    const int TB = 256;
    auto gb = [](long n, int tb) { return (int)((n + tb - 1) / tb); };
    const int PROP_BLOCKS = gb((long)NN * 32, TB);   // one warp per row

    for (int i = 0; i < 4; i++) {
        // ---- CSR build ----
        fill0_kernel<<<gb(NN / 4, TB), TB>>>((float*)DEGN, NN / 4);
        fill0_kernel<<<gb(NN / 4, TB), TB>>>((float*)DEGE, NN / 4);
        fill0_kernel<<<gb(NN / 4, TB), TB>>>((float*)CURN, NN / 4);
        fill0_kernel<<<gb(NN / 4, TB), TB>>>((float*)CURE, NN / 4);
        fill0_kernel<<<1, 32>>>((float*)CNT, 1);
        deg_kernel<<<gb(EE, TB), TB>>>(EI[i], DEGN, DEGE);
        alloc_kernel<<<gb(NN, TB), TB>>>(DEGN, DEGE, STN, STE, DINV, BINV, CNT);
        scatter_kernel<<<gb(EE, TB), TB>>>(EI[i], STN, STE, CURN, CURE, ADJN, ADJE);

        // ---- conv1: propagate X (128 dims) through H, then GEMM ----
        seg_gather_kernel<128, true ><<<PROP_BLOCKS, TB>>>(X[i], STE, DEGE, ADJE, BINV, E_);
        seg_gather_kernel<128, false><<<PROP_BLOCKS, TB>>>(E_,   STN, DEGN, ADJN, nullptr, ACC);
        gemm64_kernel<true, true><<<dim3(782, 4), TB>>>(ACC, W1, B1, DINV, C1, NN, DD1, FIN);

        // ---- conv2: GEMM to 64 dims, then propagate ----
        gemm64_kernel<false, false><<<dim3(782, 1), TB>>>(C1, W2, nullptr, nullptr, G, NN, DD2, DD1);
        seg_gather_kernel<64, true ><<<PROP_BLOCKS, TB>>>(G,  STE, DEGE, ADJE, BINV, E_);
        seg_gather_kernel<64, false><<<PROP_BLOCKS, TB>>>(E_, STN, DEGN, ADJN, nullptr, ACC);

        bias_relu_kernel<<<gb((long)NN * 64, TB), TB>>>(ACC, DINV, B2, X1 + (size_t)i * S);
        hye_kernel<<<gb(NN, 8), dim3(64, 8)>>>(X1 + (size_t)i * S, HN[i], HL[i], X2 + (size_t)i * S);
    }

    // ---- fusion attention ----
    fill0_kernel<<<1, TB>>>(WSUM, 2);
    attn_kernel<<<592, TB>>>(X1 + 1 * S, X2 + 0 * S, X1 + 2 * S, X2 + 2 * S,
                             acW1, acB1, acW2, WSUM);
    attn_kernel<<<592, TB>>>(X1 + 0 * S, X2 + 1 * S, X1 + 3 * S, X2 + 3 * S,
                             amW1, amB1, amW2, WSUM + 4);
    beta_kernel<<<1, 32>>>(WSUM, BETA);

    float* out = (float*)d_out;
    combine_kernel<<<gb((long)NN * 16, TB), TB>>>(X1 + 1 * S, X2 + 0 * S, X1 + 2 * S, X2 + 2 * S,
                                                  BETA, out);
    combine_kernel<<<gb((long)NN * 16, TB), TB>>>(X1 + 0 * S, X2 + 1 * S, X1 + 3 * S, X2 + 3 * S,
                                                  BETA + 4, out + S);
}

// round 3
// speedup vs baseline: 2.9729x; 2.6625x over previous
#include <cuda_runtime.h>
#include <math.h>
#include <stdint.h>

#define NN 50000
#define EE 800000
#define FIN 128
#define DD1 256
#define DD2 64
#define HATT 128
#define NG 4

// ---------------- scratch (device globals; no runtime allocation) ----------------
__device__ float g_E  [(size_t)NG * NN * 128];   // edge accumulator
__device__ float g_acc[(size_t)NG * NN * 128];   // node accumulator
__device__ float g_C1 [(size_t)NG * NN * 256];   // conv1 output
__device__ float g_G  [(size_t)NG * NN * 64];    // conv2 pre-propagation GEMM out
__device__ float g_x1 [(size_t)NG * NN * 64];
__device__ float g_x2 [(size_t)NG * NN * 64];
__device__ float g_dinv[NG * NN];
__device__ float g_binv[NG * NN];
__device__ float g_wsum[8];
__device__ float g_beta[8];
// CSR scratch: degn | dege | curn | cure | cnt   (one fill covers all)
__device__ int g_ws[16 * NN + 16];
__device__ int g_startn[NG * NN];
__device__ int g_starte[NG * NN];
__device__ int g_adjn[(size_t)NG * EE];   // edge ids grouped by node
__device__ int g_adje[(size_t)NG * EE];   // node ids grouped by edge

// ---------------- utility kernels ----------------
__global__ void fill0_kernel(float* __restrict__ p, int n4) {
    int t = blockIdx.x * blockDim.x + threadIdx.x;
    if (t < n4) reinterpret_cast<float4*>(p)[t] = make_float4(0.f, 0.f, 0.f, 0.f);
}

__global__ void deg_kernel(const int* e0, const int* e1, const int* e2, const int* e3,
                           int* __restrict__ dn, int* __restrict__ de)
{
    int t = blockIdx.x * blockDim.x + threadIdx.x;
    if (t < NG * EE) {
        int g = t / EE, e = t - g * EE;
        const int* ei = (g == 0) ? e0 : (g == 1) ? e1 : (g == 2) ? e2 : e3;
        atomicAdd(dn + g * NN + __ldg(ei + e), 1);
        atomicAdd(de + g * NN + __ldg(ei + e + EE), 1);
    }
}

// per-graph prefix allocation (grid.y = graph); also inverse degrees
__global__ void alloc_kernel(const int* __restrict__ degn, const int* __restrict__ dege,
                             int* __restrict__ startn, int* __restrict__ starte,
                             float* __restrict__ dinv, float* __restrict__ binv,
                             int* __restrict__ cnt)
{
    int gph = blockIdx.y;
    int t = blockIdx.x * blockDim.x + threadIdx.x;
    int lane = threadIdx.x & 31;
    int gi = gph * NN + t;
    int dn = (t < NN) ? __ldg(degn + gi) : 0;
    int de = (t < NN) ? __ldg(dege + gi) : 0;
    int sn = dn, se = de;
#pragma unroll
    for (int o = 1; o < 32; o <<= 1) {
        int vn = __shfl_up_sync(0xffffffffu, sn, o);
        int ve = __shfl_up_sync(0xffffffffu, se, o);
        if (lane >= o) { sn += vn; se += ve; }
    }
    int bn = 0, be = 0;
    if (lane == 31) {
        bn = atomicAdd(cnt + gph * 2 + 0, sn);
        be = atomicAdd(cnt + gph * 2 + 1, se);
    }
    bn = __shfl_sync(0xffffffffu, bn, 31);
    be = __shfl_sync(0xffffffffu, be, 31);
    if (t < NN) {
        startn[gi] = gph * EE + bn + sn - dn;
        starte[gi] = gph * EE + be + se - de;
        dinv[gi] = dn > 0 ? (1.0f / (float)dn) : 0.f;
        binv[gi] = de > 0 ? (1.0f / (float)de) : 0.f;
    }
}

__global__ void scatter_kernel(const int* e0, const int* e1, const int* e2, const int* e3,
                               const int* __restrict__ startn, const int* __restrict__ starte,
                               int* __restrict__ curn, int* __restrict__ cure,
                               int* __restrict__ adjn, int* __restrict__ adje)
{
    int t = blockIdx.x * blockDim.x + threadIdx.x;
    if (t < NG * EE) {
        int g = t / EE, e = t - g * EE;
        const int* ei = (g == 0) ? e0 : (g == 1) ? e1 : (g == 2) ? e2 : e3;
        int v = __ldg(ei + e);
        int h = __ldg(ei + e + EE);
        int p = atomicAdd(cure + g * NN + h, 1);
        adje[__ldg(starte + g * NN + h) + p] = v;
        int q = atomicAdd(curn + g * NN + v, 1);
        adjn[__ldg(startn + g * NN + v) + q] = h;
    }
}

// segment-sum gather over batched rows. adj holds LOCAL src indices; per-graph base ptr.
// SCALE: multiply row sum by scal[row]. FINAL: out = relu(scal[row]*sum + bias[c]).
template<int DIM, bool SCALE, bool FINAL>
__global__ __launch_bounds__(256) void seg_gather_kernel(
    const float* s0, const float* s1, const float* s2, const float* s3,
    const int* __restrict__ start, const int* __restrict__ deg,
    const int* __restrict__ adj, const float* __restrict__ scal,
    const float* __restrict__ bias, float* __restrict__ dst)
{
    int warp = (blockIdx.x * blockDim.x + threadIdx.x) >> 5;
    int lane = threadIdx.x & 31;
    if (warp >= NG * NN) return;
    int g = warp / NN;
    const float* src = (g == 0) ? s0 : (g == 1) ? s1 : (g == 2) ? s2 : s3;
    int s = __ldg(start + warp);
    int d = __ldg(deg + warp);
    if (DIM == 128) {
        const float4* S = reinterpret_cast<const float4*>(src);
        float4 a = make_float4(0.f, 0.f, 0.f, 0.f);
        int k = 0;
        for (; k + 4 <= d; k += 4) {
            int j0 = __ldg(adj + s + k + 0), j1 = __ldg(adj + s + k + 1);
            int j2 = __ldg(adj + s + k + 2), j3 = __ldg(adj + s + k + 3);
            float4 v0 = __ldg(S + ((size_t)j0 << 5) + lane);
            float4 v1 = __ldg(S + ((size_t)j1 << 5) + lane);
            float4 v2 = __ldg(S + ((size_t)j2 << 5) + lane);
            float4 v3 = __ldg(S + ((size_t)j3 << 5) + lane);
            a.x += (v0.x + v1.x) + (v2.x + v3.x);
            a.y += (v0.y + v1.y) + (v2.y + v3.y);
            a.z += (v0.z + v1.z) + (v2.z + v3.z);
            a.w += (v0.w + v1.w) + (v2.w + v3.w);
        }
        for (; k < d; k++) {
            int j = __ldg(adj + s + k);
            float4 v = __ldg(S + ((size_t)j << 5) + lane);
            a.x += v.x; a.y += v.y; a.z += v.z; a.w += v.w;
        }
        if (SCALE) { float b = __ldg(scal + warp); a.x *= b; a.y *= b; a.z *= b; a.w *= b; }
        reinterpret_cast<float4*>(dst)[((size_t)warp << 5) + lane] = a;
    } else {   // DIM == 64, two columns per lane
        const float2* S = reinterpret_cast<const float2*>(src);
        float2 a = make_float2(0.f, 0.f);
        int k = 0;
        for (; k + 4 <= d; k += 4) {
            int j0 = __ldg(adj + s + k + 0), j1 = __ldg(adj + s + k + 1);
            int j2 = __ldg(adj + s + k + 2), j3 = __ldg(adj + s + k + 3);
            float2 v0 = __ldg(S + ((size_t)j0 << 5) + lane);
            float2 v1 = __ldg(S + ((size_t)j1 << 5) + lane);
            float2 v2 = __ldg(S + ((size_t)j2 << 5) + lane);
            float2 v3 = __ldg(S + ((size_t)j3 << 5) + lane);
            a.x += (v0.x + v1.x) + (v2.x + v3.x);
            a.y += (v0.y + v1.y) + (v2.y + v3.y);
        }
        for (; k < d; k++) {
            int j = __ldg(adj + s + k);
            float2 v = __ldg(S + ((size_t)j << 5) + lane);
            a.x += v.x; a.y += v.y;
        }
        if (FINAL) {
            float dv = __ldg(scal + warp);
            float2 bb = __ldg(reinterpret_cast<const float2*>(bias) + lane);
            a.x = fmaxf(fmaf(dv, a.x, bb.x), 0.f);
            a.y = fmaxf(fmaf(dv, a.y, bb.y), 0.f);
        } else if (SCALE) {
            float b = __ldg(scal + warp);
            a.x *= b; a.y *= b;
        }
        reinterpret_cast<float2*>(dst)[((size_t)warp << 5) + lane] = a;
    }
}

// ---------------- GEMM: C[M,Nn] = A[M,K] @ B[K,Nn] ----------------
// BM=128, 256 threads, TM=8 x TN per thread. EPI: rowscale+bias+relu.
template<int BN, int TN, bool EPI>
__global__ __launch_bounds__(256) void gemm_kernel(
    const float* __restrict__ A, const float* __restrict__ Bm,
    const float* __restrict__ bias, const float* __restrict__ rs,
    float* __restrict__ C, int M, int Nn, int K)
{
    const int BM = 128, BK = 16, TM = 8;
    __shared__ __align__(16) float As[BK][BM + 4];
    __shared__ __align__(16) float Bs[BK][BN + 4];
    int tid = threadIdx.x;
    int bm = blockIdx.x * BM, bn = blockIdx.y * BN;
    int tx = tid & 15, ty = tid >> 4;
    int ar = tid >> 1, ak = (tid & 1) * 8;          // A tile: 128 rows x 16 k
    int bkr = tid >> 4, bnc = (tid & 15) * (BN / 16); // B tile: 16 k x BN
    float acc[TM][TN] = {};
    for (int k0 = 0; k0 < K; k0 += BK) {
        float4 av0 = make_float4(0.f, 0.f, 0.f, 0.f), av1 = av0;
        if (bm + ar < M) {
            const float* ap = A + (size_t)(bm + ar) * K + k0 + ak;
            av0 = *reinterpret_cast<const float4*>(ap);
            av1 = *reinterpret_cast<const float4*>(ap + 4);
        }
        As[ak + 0][ar] = av0.x; As[ak + 1][ar] = av0.y;
        As[ak + 2][ar] = av0.z; As[ak + 3][ar] = av0.w;
        As[ak + 4][ar] = av1.x; As[ak + 5][ar] = av1.y;
        As[ak + 6][ar] = av1.z; As[ak + 7][ar] = av1.w;
        const float* bp = Bm + (size_t)(k0 + bkr) * Nn + bn + bnc;
        if (BN == 128) {
            float4 b0 = *reinterpret_cast<const float4*>(bp);
            float4 b1 = *reinterpret_cast<const float4*>(bp + 4);
            *reinterpret_cast<float4*>(&Bs[bkr][bnc]) = b0;
            *reinterpret_cast<float4*>(&Bs[bkr][bnc + 4]) = b1;
        } else {
            float4 b0 = *reinterpret_cast<const float4*>(bp);
            *reinterpret_cast<float4*>(&Bs[bkr][bnc]) = b0;
        }
        __syncthreads();
#pragma unroll
        for (int kk = 0; kk < BK; kk++) {
            float a[TM], b[TN];
            float4 a0 = *reinterpret_cast<float4*>(&As[kk][ty * TM]);
            float4 a1 = *reinterpret_cast<float4*>(&As[kk][ty * TM + 4]);
            a[0] = a0.x; a[1] = a0.y; a[2] = a0.z; a[3] = a0.w;
            a[4] = a1.x; a[5] = a1.y; a[6] = a1.z; a[7] = a1.w;
            float4 b0 = *reinterpret_cast<float4*>(&Bs[kk][tx * TN]);
            b[0] = b0.x; b[1] = b0.y; b[2] = b0.z; b[3] = b0.w;
            if (TN == 8) {
                float4 b1 = *reinterpret_cast<float4*>(&Bs[kk][tx * TN + 4]);
                b[4] = b1.x; b[5] = b1.y; b[6] = b1.z; b[7] = b1.w;
            }
#pragma unroll
            for (int i = 0; i < TM; i++)
#pragma unroll
                for (int j = 0; j < TN; j++)
                    acc[i][j] = fmaf(a[i], b[j], acc[i][j]);
        }
        __syncthreads();
    }
#pragma unroll
    for (int i = 0; i < TM; i++) {
        int m = bm + ty * TM + i;
        if (m < M) {
            float sc = EPI ? __ldg(rs + m) : 1.0f;
            float* cp = C + (size_t)m * Nn + bn + tx * TN;
#pragma unroll
            for (int j = 0; j < TN; j++) {
                float v = acc[i][j] * sc;
                if (EPI) v = fmaxf(v + __ldg(bias + bn + tx * TN + j), 0.f);
                cp[j] = v;
            }
        }
    }
}

// hyperedge embedding, batched over 4 graphs
__global__ void hye_kernel(const float* __restrict__ x1,
                           const int* h0, const int* h1, const int* h2, const int* h3,
                           const float* l0, const float* l1, const float* l2, const float* l3,
                           float* __restrict__ x2)
{
    int n = blockIdx.x * blockDim.y + threadIdx.y;
    if (n >= NG * NN) return;
    int g = n / NN, ln = n - g * NN;
    const int* hnode = (g == 0) ? h0 : (g == 1) ? h1 : (g == 2) ? h2 : h3;
    const float* hlen = (g == 0) ? l0 : (g == 1) ? l1 : (g == 2) ? l2 : l3;
    int c = threadIdx.x;   // 0..63
    const float* base = x1 + (size_t)g * NN * 64;
    float s = 0.f;
#pragma unroll
    for (int l = 0; l < 16; l++) {
        int j = __ldg(hnode + (size_t)ln * 16 + l);
        if (j > 0) s += __ldg(base + (size_t)(j - 1) * 64 + c);
    }
    x2[(size_t)n * 64 + c] = s / (__ldg(hlen + ln) + 1e-15f);
}

// fusion-attention scores
__global__ __launch_bounds__(256) void attn_kernel(
    const float* __restrict__ z0, const float* __restrict__ z1,
    const float* __restrict__ z2, const float* __restrict__ z3,
    const float* __restrict__ W1, const float* __restrict__ b1,
    const float* __restrict__ W2, float* __restrict__ wsum)
{
    __shared__ __align__(16) float sW1[64 * 128];
    __shared__ __align__(16) float sb1[128];
    __shared__ __align__(16) float sW2[128];
    for (int i = threadIdx.x; i < 64 * 128; i += 256) sW1[i] = W1[i];
    if (threadIdx.x < 128) { sb1[threadIdx.x] = b1[threadIdx.x]; sW2[threadIdx.x] = W2[threadIdx.x]; }
    __syncthreads();
    const float* zs[4] = {z0, z1, z2, z3};
    int warp = threadIdx.x >> 5, lane = threadIdx.x & 31;
    float accs[4] = {0.f, 0.f, 0.f, 0.f};
    float4 hb = *reinterpret_cast<const float4*>(&sb1[lane << 2]);
    float4 w2 = *reinterpret_cast<const float4*>(&sW2[lane << 2]);
    for (int n = blockIdx.x * 8 + warp; n < NN; n += gridDim.x * 8) {
#pragma unroll
        for (int s = 0; s < 4; s++) {
            const float* v = zs[s] + (size_t)n * 64;
            float h0 = hb.x, h1 = hb.y, h2 = hb.z, h3 = hb.w;
#pragma unroll
            for (int k4 = 0; k4 < 16; k4++) {
                float4 v4 = __ldg(reinterpret_cast<const float4*>(v) + k4);
                float vv[4] = {v4.x, v4.y, v4.z, v4.w};
#pragma unroll
                for (int ss = 0; ss < 4; ss++) {
                    float4 w = *reinterpret_cast<const float4*>(&sW1[(k4 * 4 + ss) * 128 + (lane << 2)]);
                    h0 = fmaf(vv[ss], w.x, h0); h1 = fmaf(vv[ss], w.y, h1);
                    h2 = fmaf(vv[ss], w.z, h2); h3 = fmaf(vv[ss], w.w, h3);
                }
            }
            float r = tanhf(h0) * w2.x + tanhf(h1) * w2.y + tanhf(h2) * w2.z + tanhf(h3) * w2.w;
#pragma unroll
            for (int o = 16; o; o >>= 1) r += __shfl_xor_sync(0xffffffffu, r, o);
            if (lane == 0) accs[s] += r;
        }
    }
    if (lane == 0) {
#pragma unroll
        for (int s = 0; s < 4; s++) atomicAdd(wsum + s, accs[s]);
    }
}

__global__ void beta_kernel(const float* __restrict__ wsum, float* __restrict__ beta) {
    if (threadIdx.x == 0 && blockIdx.x == 0) {
        for (int h = 0; h < 2; h++) {
            float v[4], m = -1e30f;
            for (int s = 0; s < 4; s++) { v[s] = wsum[h * 4 + s] / (float)NN; if (v[s] > m) m = v[s]; }
            float sum = 0.f;
            for (int s = 0; s < 4; s++) { v[s] = expf(v[s] - m); sum += v[s]; }
            for (int s = 0; s < 4; s++) beta[h * 4 + s] = v[s] / sum;
        }
    }
}

__global__ void combine_kernel(const float* __restrict__ z0, const float* __restrict__ z1,
                               const float* __restrict__ z2, const float* __restrict__ z3,
                               const float* __restrict__ beta, float* __restrict__ out)
{
    int t = blockIdx.x * blockDim.x + threadIdx.x;
    if (t < NN * 16) {
        float b0 = __ldg(beta + 0), b1 = __ldg(beta + 1), b2 = __ldg(beta + 2), b3 = __ldg(beta + 3);
        float4 a = __ldg(reinterpret_cast<const float4*>(z0) + t);
        float4 b = __ldg(reinterpret_cast<const float4*>(z1) + t);
        float4 c = __ldg(reinterpret_cast<const float4*>(z2) + t);
        float4 d = __ldg(reinterpret_cast<const float4*>(z3) + t);
        float4 o;
        o.x = b0 * a.x + b1 * b.x + b2 * c.x + b3 * d.x;
        o.y = b0 * a.y + b1 * b.y + b2 * c.y + b3 * d.y;
        o.z = b0 * a.z + b1 * b.z + b2 * c.z + b3 * d.z;
        o.w = b0 * a.w + b1 * b.w + b2 * c.w + b3 * d.w;
        reinterpret_cast<float4*>(out)[t] = o;
    }
}

// ---------------- host launcher ----------------
extern "C" void kernel_launch(void* const* d_in, const int* in_sizes, int n_in,
                              void* d_out, int out_size)
{
    int xi[4], eii[4], hni[4], hli[4];
    int nx = 0, ne = 0, nh = 0, nl = 0;
    int iW1 = -1, ib1 = -1, iW2 = -1, ib2 = -1;
    int i8192[2]; int n8 = 0;
    int i128[4];  int n128 = 0;
    for (int i = 0; i < n_in; i++) {
        switch (in_sizes[i]) {
            case NN * FIN:   if (nx < 4) xi[nx++] = i; break;
            case 2 * EE:     if (ne < 4) eii[ne++] = i; break;
            case NN * 16:    if (nh < 4) hni[nh++] = i; break;
            case NN:         if (nl < 4) hli[nl++] = i; break;
            case FIN * DD1:  iW1 = i; break;
            case DD1:        ib1 = i; break;
            case DD1 * DD2:  iW2 = i; break;
            case DD2:        ib2 = i; break;
            case DD2 * HATT: if (n8 < 2) i8192[n8++] = i; break;
            case HATT:       if (n128 < 4) i128[n128++] = i; break;
            default: break;
        }
    }
    const float* X[4]; const int* EI[4];
    const int* HN[4]; const float* HL[4];
    for (int i = 0; i < 4; i++) {
        X[i]  = (const float*)d_in[xi[i]];
        EI[i] = (const int*)d_in[eii[i]];
        HN[i] = (const int*)d_in[hni[i]];
        HL[i] = (const float*)d_in[hli[i]];
    }
    const float* W1 = (const float*)d_in[iW1];
    const float* B1 = (const float*)d_in[ib1];
    const float* W2 = (const float*)d_in[iW2];
    const float* B2 = (const float*)d_in[ib2];
    const float* acW1 = (const float*)d_in[i8192[0]];
    const float* amW1 = (const float*)d_in[i8192[1]];
    const float* acB1 = (const float*)d_in[i128[0]];
    const float* acW2 = (const float*)d_in[i128[1]];
    const float* amB1 = (const float*)d_in[i128[2]];
    const float* amW2 = (const float*)d_in[i128[3]];

    float *E_, *ACC, *C1, *G, *X1, *X2, *DINV, *BINV, *WSUM, *BETA;
    int *WS, *STN, *STE, *ADJN, *ADJE;
    cudaGetSymbolAddress((void**)&E_,   g_E);
    cudaGetSymbolAddress((void**)&ACC,  g_acc);
    cudaGetSymbolAddress((void**)&C1,   g_C1);
    cudaGetSymbolAddress((void**)&G,    g_G);
    cudaGetSymbolAddress((void**)&X1,   g_x1);
    cudaGetSymbolAddress((void**)&X2,   g_x2);
    cudaGetSymbolAddress((void**)&DINV, g_dinv);
    cudaGetSymbolAddress((void**)&BINV, g_binv);
    cudaGetSymbolAddress((void**)&WSUM, g_wsum);
    cudaGetSymbolAddress((void**)&BETA, g_beta);
    cudaGetSymbolAddress((void**)&WS,   g_ws);
    cudaGetSymbolAddress((void**)&STN,  g_startn);
    cudaGetSymbolAddress((void**)&STE,  g_starte);
    cudaGetSymbolAddress((void**)&ADJN, g_adjn);
    cudaGetSymbolAddress((void**)&ADJE, g_adje);
    int* DEGN = WS;
    int* DEGE = WS + 4 * NN;
    int* CURN = WS + 8 * NN;
    int* CURE = WS + 12 * NN;
    int* CNT  = WS + 16 * NN;

    const size_t S = (size_t)NN * 64;
    const int TB = 256;
    auto gb = [](long n, int tb) { return (int)((n + tb - 1) / tb); };
    const int PROP_BLOCKS = gb((long)NG * NN * 32, TB);   // one warp per row
    const int MB = NG * NN;                               // batched M

    // ---- CSR build (all graphs) ----
    fill0_kernel<<<gb((16 * NN + 16) / 4, TB), TB>>>((float*)WS, (16 * NN + 16) / 4);
    deg_kernel<<<gb((long)NG * EE, TB), TB>>>(EI[0], EI[1], EI[2], EI[3], DEGN, DEGE);
    alloc_kernel<<<dim3(gb(NN, TB), NG), TB>>>(DEGN, DEGE, STN, STE, DINV, BINV, CNT);
    scatter_kernel<<<gb((long)NG * EE, TB), TB>>>(EI[0], EI[1], EI[2], EI[3],
                                                  STN, STE, CURN, CURE, ADJN, ADJE);

    // ---- conv1: propagate X (128 dims) through H, then GEMM (rowscale+bias+relu) ----
    seg_gather_kernel<128, true, false><<<PROP_BLOCKS, TB>>>(
        X[0], X[1], X[2], X[3], STE, DEGE, ADJE, BINV, nullptr, E_);
    {
        const float* e0 = E_;
        seg_gather_kernel<128, false, false><<<PROP_BLOCKS, TB>>>(
            e0, e0 + S * 2, e0 + S * 4, e0 + S * 6, STN, DEGN, ADJN, nullptr, nullptr, ACC);
    }
    gemm_kernel<128, 8, true><<<dim3(gb(MB, 128), 2), TB>>>(ACC, W1, B1, DINV, C1, MB, DD1, FIN);

    // ---- conv2: GEMM to 64 dims, then propagate, fused dinv+bias+relu ----
    gemm_kernel<64, 4, false><<<dim3(gb(MB, 128), 1), TB>>>(C1, W2, nullptr, nullptr, G, MB, DD2, DD1);
    seg_gather_kernel<64, true, false><<<PROP_BLOCKS, TB>>>(
        G, G + S, G + S * 2, G + S * 3, STE, DEGE, ADJE, BINV, nullptr, E_);
    {
        const float* e0 = E_;
        seg_gather_kernel<64, false, true><<<PROP_BLOCKS, TB>>>(
            e0, e0 + S, e0 + S * 2, e0 + S * 3, STN, DEGN, ADJN, DINV, B2, X1);
    }

    // ---- hyperedge embeddings (batched) ----
    hye_kernel<<<gb((long)NG * NN, 8), dim3(64, 8)>>>(
        X1, HN[0], HN[1], HN[2], HN[3], HL[0], HL[1], HL[2], HL[3], X2);

    // ---- fusion attention ----
    fill0_kernel<<<1, TB>>>(WSUM, 2);
    attn_kernel<<<592, TB>>>(X1 + 1 * S, X2 + 0 * S, X1 + 2 * S, X2 + 2 * S,
                             acW1, acB1, acW2, WSUM);
    attn_kernel<<<592, TB>>>(X1 + 0 * S, X2 + 1 * S, X1 + 3 * S, X2 + 3 * S,
                             amW1, amB1, amW2, WSUM + 4);
    beta_kernel<<<1, 32>>>(WSUM, BETA);

    float* out = (float*)d_out;
    combine_kernel<<<gb((long)NN * 16, TB), TB>>>(X1 + 1 * S, X2 + 0 * S, X1 + 2 * S, X2 + 2 * S,
                                                  BETA, out);
    combine_kernel<<<gb((long)NN * 16, TB), TB>>>(X1 + 0 * S, X2 + 1 * S, X1 + 3 * S, X2 + 3 * S,
                                                  BETA + 4, out + S);
}

// round 5
// speedup vs baseline: 3.7802x; 1.2716x over previous
#include <cuda_runtime.h>
#include <math.h>
#include <stdint.h>

#define NN 50000
#define EE 800000
#define FIN 128
#define DD1 256
#define DD2 64
#define HATT 128
#define NG 4
#define MP 200064   // NG*NN padded to multiple of 128 (1563*128)

// ---------------- scratch (device globals; zero-initialized, no runtime alloc) ----
__device__ float g_E  [(size_t)NG * NN * 128];   // edge accumulator
__device__ float g_acc[(size_t)MP * 128];        // node accumulator (padded M)
__device__ float g_C1 [(size_t)MP * 256];        // conv1 output (padded M)
__device__ float g_G  [(size_t)MP * 64];         // conv2 GEMM out (padded M)
__device__ float g_x1 [(size_t)NG * NN * 64];
__device__ float g_x2 [(size_t)NG * NN * 64];
__device__ float g_dinv[MP];
__device__ float g_binv[NG * NN];
__device__ float g_wsum[8];
__device__ float g_beta[8];
// CSR scratch: degn | dege | curn | cure | cnt
__device__ int g_ws[16 * NN + 16];
__device__ int g_startn[NG * NN];
__device__ int g_starte[NG * NN];
__device__ int g_adjn[(size_t)NG * EE];
__device__ int g_adje[(size_t)NG * EE];

// ---------------- small helpers ----------------
__device__ __forceinline__ unsigned f2tf(float f) {
    unsigned r; asm("cvt.rna.tf32.f32 %0, %1;" : "=r"(r) : "f"(f)); return r;
}
__device__ __forceinline__ void mma8(float& c0, float& c1, float& c2, float& c3,
                                     unsigned a0, unsigned a1, unsigned a2, unsigned a3,
                                     unsigned b0, unsigned b1) {
    asm volatile("mma.sync.aligned.m16n8k8.row.col.f32.tf32.tf32.f32 "
                 "{%0,%1,%2,%3}, {%4,%5,%6,%7}, {%8,%9}, {%0,%1,%2,%3};"
                 : "+f"(c0), "+f"(c1), "+f"(c2), "+f"(c3)
                 : "r"(a0), "r"(a1), "r"(a2), "r"(a3), "r"(b0), "r"(b1));
}
__device__ __forceinline__ void cpa16(void* dst_smem, const void* src) {
    unsigned d = (unsigned)__cvta_generic_to_shared(dst_smem);
    asm volatile("cp.async.ca.shared.global [%0], [%1], 16;" :: "r"(d), "l"(src));
}

// ---------------- utility kernels ----------------
__global__ void fill0_kernel(float* __restrict__ p, int n4) {
    int t = blockIdx.x * blockDim.x + threadIdx.x;
    if (t < n4) reinterpret_cast<float4*>(p)[t] = make_float4(0.f, 0.f, 0.f, 0.f);
}

__global__ void deg_kernel(const int* e0, const int* e1, const int* e2, const int* e3,
                           int* __restrict__ dn, int* __restrict__ de)
{
    int t = blockIdx.x * blockDim.x + threadIdx.x;
    if (t < NG * EE) {
        int g = t / EE, e = t - g * EE;
        const int* ei = (g == 0) ? e0 : (g == 1) ? e1 : (g == 2) ? e2 : e3;
        atomicAdd(dn + g * NN + __ldg(ei + e), 1);
        atomicAdd(de + g * NN + __ldg(ei + e + EE), 1);
    }
}

__global__ void alloc_kernel(const int* __restrict__ degn, const int* __restrict__ dege,
                             int* __restrict__ startn, int* __restrict__ starte,
                             float* __restrict__ dinv, float* __restrict__ binv,
                             int* __restrict__ cnt)
{
    int gph = blockIdx.y;
    int t = blockIdx.x * blockDim.x + threadIdx.x;
    int lane = threadIdx.x & 31;
    int gi = gph * NN + t;
    int dn = (t < NN) ? __ldg(degn + gi) : 0;
    int de = (t < NN) ? __ldg(dege + gi) : 0;
    int sn = dn, se = de;
#pragma unroll
    for (int o = 1; o < 32; o <<= 1) {
        int vn = __shfl_up_sync(0xffffffffu, sn, o);
        int ve = __shfl_up_sync(0xffffffffu, se, o);
        if (lane >= o) { sn += vn; se += ve; }
    }
    int bn = 0, be = 0;
    if (lane == 31) {
        bn = atomicAdd(cnt + gph * 2 + 0, sn);
        be = atomicAdd(cnt + gph * 2 + 1, se);
    }
    bn = __shfl_sync(0xffffffffu, bn, 31);
    be = __shfl_sync(0xffffffffu, be, 31);
    if (t < NN) {
        startn[gi] = gph * EE + bn + sn - dn;
        starte[gi] = gph * EE + be + se - de;
        dinv[gi] = dn > 0 ? (1.0f / (float)dn) : 0.f;
        binv[gi] = de > 0 ? (1.0f / (float)de) : 0.f;
    }
}

__global__ void scatter_kernel(const int* e0, const int* e1, const int* e2, const int* e3,
                               const int* __restrict__ startn, const int* __restrict__ starte,
                               int* __restrict__ curn, int* __restrict__ cure,
                               int* __restrict__ adjn, int* __restrict__ adje)
{
    int t = blockIdx.x * blockDim.x + threadIdx.x;
    if (t < NG * EE) {
        int g = t / EE, e = t - g * EE;
        const int* ei = (g == 0) ? e0 : (g == 1) ? e1 : (g == 2) ? e2 : e3;
        int v = __ldg(ei + e);
        int h = __ldg(ei + e + EE);
        int p = atomicAdd(cure + g * NN + h, 1);
        adje[__ldg(starte + g * NN + h) + p] = v;
        int q = atomicAdd(curn + g * NN + v, 1);
        adjn[__ldg(startn + g * NN + v) + q] = h;
    }
}

// segment-sum gather over batched rows.
template<int DIM, bool SCALE, bool FINAL>
__global__ __launch_bounds__(256) void seg_gather_kernel(
    const float* s0, const float* s1, const float* s2, const float* s3,
    const int* __restrict__ start, const int* __restrict__ deg,
    const int* __restrict__ adj, const float* __restrict__ scal,
    const float* __restrict__ bias, float* __restrict__ dst)
{
    int warp = (blockIdx.x * blockDim.x + threadIdx.x) >> 5;
    int lane = threadIdx.x & 31;
    if (warp >= NG * NN) return;
    int g = warp / NN;
    const float* src = (g == 0) ? s0 : (g == 1) ? s1 : (g == 2) ? s2 : s3;
    int s = __ldg(start + warp);
    int d = __ldg(deg + warp);
    if (DIM == 128) {
        const float4* S = reinterpret_cast<const float4*>(src);
        float4 a = make_float4(0.f, 0.f, 0.f, 0.f);
        int k = 0;
        for (; k + 4 <= d; k += 4) {
            int j0 = __ldg(adj + s + k + 0), j1 = __ldg(adj + s + k + 1);
            int j2 = __ldg(adj + s + k + 2), j3 = __ldg(adj + s + k + 3);
            float4 v0 = __ldg(S + ((size_t)j0 << 5) + lane);
            float4 v1 = __ldg(S + ((size_t)j1 << 5) + lane);
            float4 v2 = __ldg(S + ((size_t)j2 << 5) + lane);
            float4 v3 = __ldg(S + ((size_t)j3 << 5) + lane);
            a.x += (v0.x + v1.x) + (v2.x + v3.x);
            a.y += (v0.y + v1.y) + (v2.y + v3.y);
            a.z += (v0.z + v1.z) + (v2.z + v3.z);
            a.w += (v0.w + v1.w) + (v2.w + v3.w);
        }
        for (; k < d; k++) {
            int j = __ldg(adj + s + k);
            float4 v = __ldg(S + ((size_t)j << 5) + lane);
            a.x += v.x; a.y += v.y; a.z += v.z; a.w += v.w;
        }
        if (SCALE) { float b = __ldg(scal + warp); a.x *= b; a.y *= b; a.z *= b; a.w *= b; }
        reinterpret_cast<float4*>(dst)[((size_t)warp << 5) + lane] = a;
    } else {
        const float2* S = reinterpret_cast<const float2*>(src);
        float2 a = make_float2(0.f, 0.f);
        int k = 0;
        for (; k + 4 <= d; k += 4) {
            int j0 = __ldg(adj + s + k + 0), j1 = __ldg(adj + s + k + 1);
            int j2 = __ldg(adj + s + k + 2), j3 = __ldg(adj + s + k + 3);
            float2 v0 = __ldg(S + ((size_t)j0 << 5) + lane);
            float2 v1 = __ldg(S + ((size_t)j1 << 5) + lane);
            float2 v2 = __ldg(S + ((size_t)j2 << 5) + lane);
            float2 v3 = __ldg(S + ((size_t)j3 << 5) + lane);
            a.x += (v0.x + v1.x) + (v2.x + v3.x);
            a.y += (v0.y + v1.y) + (v2.y + v3.y);
        }
        for (; k < d; k++) {
            int j = __ldg(adj + s + k);
            float2 v = __ldg(S + ((size_t)j << 5) + lane);
            a.x += v.x; a.y += v.y;
        }
        if (FINAL) {
            float dv = __ldg(scal + warp);
            float2 bb = __ldg(reinterpret_cast<const float2*>(bias) + lane);
            a.x = fmaxf(fmaf(dv, a.x, bb.x), 0.f);
            a.y = fmaxf(fmaf(dv, a.y, bb.y), 0.f);
        } else if (SCALE) {
            float b = __ldg(scal + warp);
            a.x *= b; a.y *= b;
        }
        reinterpret_cast<float2*>(dst)[((size_t)warp << 5) + lane] = a;
    }
}

// ---------------- tf32 tensor-core GEMM: C[M,Nn] = A[M,K] @ B[K,Nn] ----------------
// BM=128, BK=32, 256 threads (8 warps in WR x WC grid). M must be a multiple of 128.
// EPI: C = relu(rowscale*acc + bias).
template<int BN, int WR, int WC, bool EPI>
__global__ __launch_bounds__(256) void mma_gemm_kernel(
    const float* __restrict__ A, const float* __restrict__ Bm,
    const float* __restrict__ bias, const float* __restrict__ rs,
    float* __restrict__ C, int Nn, int K)
{
    const int BM = 128, BK = 32;
    const int WM = BM / WR, WN = BN / WC;
    const int MT = WM / 16, NT = WN / 8;
    __shared__ __align__(16) float As[BM][BK + 4];
    __shared__ __align__(16) float Bs[BK][BN + 4];
    int tid = threadIdx.x;
    int warp = tid >> 5, lane = tid & 31;
    int wm = (warp / WC) * WM;
    int wn = (warp % WC) * WN;
    size_t bm = (size_t)blockIdx.x * BM;
    int bn = blockIdx.y * BN;
    float acc[MT][NT][4] = {};

    for (int k0 = 0; k0 < K; k0 += BK) {
        // A tile: 128x32 floats = 1024 float4 -> 4 per thread
#pragma unroll
        for (int i = 0; i < 4; i++) {
            int c = tid + i * 256;
            int r = c >> 3, k4 = (c & 7) << 2;
            cpa16(&As[r][k4], A + (bm + r) * K + k0 + k4);
        }
        // B tile: 32xBN floats
#pragma unroll
        for (int i = 0; i < (BK * BN / 4) / 256; i++) {
            int c = tid + i * 256;
            int r = c / (BN / 4), n4 = (c % (BN / 4)) << 2;
            cpa16(&Bs[r][n4], Bm + (size_t)(k0 + r) * Nn + bn + n4);
        }
        asm volatile("cp.async.commit_group;");
        asm volatile("cp.async.wait_group 0;");
        __syncthreads();
#pragma unroll
        for (int ks = 0; ks < BK / 8; ks++) {
            unsigned af[MT][4], bf[NT][2];
            int kb = ks * 8 + (lane & 3);
            int rr = lane >> 2;
#pragma unroll
            for (int mt = 0; mt < MT; mt++) {
                int r = wm + mt * 16 + rr;
                af[mt][0] = f2tf(As[r][kb]);
                af[mt][1] = f2tf(As[r + 8][kb]);
                af[mt][2] = f2tf(As[r][kb + 4]);
                af[mt][3] = f2tf(As[r + 8][kb + 4]);
            }
#pragma unroll
            for (int nt = 0; nt < NT; nt++) {
                int n = wn + nt * 8 + rr;
                bf[nt][0] = f2tf(Bs[kb][n]);
                bf[nt][1] = f2tf(Bs[kb + 4][n]);
            }
#pragma unroll
            for (int mt = 0; mt < MT; mt++)
#pragma unroll
                for (int nt = 0; nt < NT; nt++)
                    mma8(acc[mt][nt][0], acc[mt][nt][1], acc[mt][nt][2], acc[mt][nt][3],
                         af[mt][0], af[mt][1], af[mt][2], af[mt][3],
                         bf[nt][0], bf[nt][1]);
        }
        __syncthreads();
    }
    // epilogue
#pragma unroll
    for (int mt = 0; mt < MT; mt++) {
        size_t r0 = bm + wm + mt * 16 + (lane >> 2);
#pragma unroll
        for (int half = 0; half < 2; half++) {
            size_t r = r0 + half * 8;
            float sc = EPI ? __ldg(rs + r) : 1.0f;
#pragma unroll
            for (int nt = 0; nt < NT; nt++) {
                int col = bn + wn + nt * 8 + (lane & 3) * 2;
                float v0 = acc[mt][nt][half * 2 + 0];
                float v1 = acc[mt][nt][half * 2 + 1];
                if (EPI) {
                    v0 = fmaxf(fmaf(v0, sc, __ldg(bias + col)), 0.f);
                    v1 = fmaxf(fmaf(v1, sc, __ldg(bias + col + 1)), 0.f);
                }
                *reinterpret_cast<float2*>(C + r * Nn + col) = make_float2(v0, v1);
            }
        }
    }
}

// hyperedge embedding, batched over 4 graphs
__global__ void hye_kernel(const float* __restrict__ x1,
                           const int* h0, const int* h1, const int* h2, const int* h3,
                           const float* l0, const float* l1, const float* l2, const float* l3,
                           float* __restrict__ x2)
{
    int n = blockIdx.x * blockDim.y + threadIdx.y;
    if (n >= NG * NN) return;
    int g = n / NN, ln = n - g * NN;
    const int* hnode = (g == 0) ? h0 : (g == 1) ? h1 : (g == 2) ? h2 : h3;
    const float* hlen = (g == 0) ? l0 : (g == 1) ? l1 : (g == 2) ? l2 : l3;
    int c = threadIdx.x;   // 0..63
    const float* base = x1 + (size_t)g * NN * 64;
    float s = 0.f;
#pragma unroll
    for (int l = 0; l < 16; l++) {
        int j = __ldg(hnode + (size_t)ln * 16 + l);
        if (j > 0) s += __ldg(base + (size_t)(j - 1) * 64 + c);
    }
    x2[(size_t)n * 64 + c] = s / (__ldg(hlen + ln) + 1e-15f);
}

// fusion-attention scores, both heads in one launch (grid.y = head)
__global__ __launch_bounds__(256) void attn_kernel(
    const float* c0, const float* c1, const float* c2, const float* c3,
    const float* m0, const float* m1, const float* m2, const float* m3,
    const float* acW1, const float* acB1, const float* acW2,
    const float* amW1, const float* amB1, const float* amW2,
    float* __restrict__ wsum)
{
    int head = blockIdx.y;
    const float* W1 = head ? amW1 : acW1;
    const float* b1 = head ? amB1 : acB1;
    const float* W2 = head ? amW2 : acW2;
    const float* zs[4];
    if (head == 0) { zs[0] = c0; zs[1] = c1; zs[2] = c2; zs[3] = c3; }
    else           { zs[0] = m0; zs[1] = m1; zs[2] = m2; zs[3] = m3; }
    wsum += head * 4;

    __shared__ __align__(16) float sW1[64 * 128];
    __shared__ __align__(16) float sb1[128];
    __shared__ __align__(16) float sW2[128];
    for (int i = threadIdx.x; i < 64 * 128; i += 256) sW1[i] = W1[i];
    if (threadIdx.x < 128) { sb1[threadIdx.x] = b1[threadIdx.x]; sW2[threadIdx.x] = W2[threadIdx.x]; }
    __syncthreads();
    int warp = threadIdx.x >> 5, lane = threadIdx.x & 31;
    float accs[4] = {0.f, 0.f, 0.f, 0.f};
    float4 hb = *reinterpret_cast<const float4*>(&sb1[lane << 2]);
    float4 w2 = *reinterpret_cast<const float4*>(&sW2[lane << 2]);
    for (int n = blockIdx.x * 8 + warp; n < NN; n += gridDim.x * 8) {
#pragma unroll
        for (int s = 0; s < 4; s++) {
            const float* v = zs[s] + (size_t)n * 64;
            float h0 = hb.x, h1 = hb.y, h2 = hb.z, h3 = hb.w;
#pragma unroll
            for (int k4 = 0; k4 < 16; k4++) {
                float4 v4 = __ldg(reinterpret_cast<const float4*>(v) + k4);
                float vv[4] = {v4.x, v4.y, v4.z, v4.w};
#pragma unroll
                for (int ss = 0; ss < 4; ss++) {
                    float4 w = *reinterpret_cast<const float4*>(&sW1[(k4 * 4 + ss) * 128 + (lane << 2)]);
                    h0 = fmaf(vv[ss], w.x, h0); h1 = fmaf(vv[ss], w.y, h1);
                    h2 = fmaf(vv[ss], w.z, h2); h3 = fmaf(vv[ss], w.w, h3);
                }
            }
            float r = tanhf(h0) * w2.x + tanhf(h1) * w2.y + tanhf(h2) * w2.z + tanhf(h3) * w2.w;
#pragma unroll
            for (int o = 16; o; o >>= 1) r += __shfl_xor_sync(0xffffffffu, r, o);
            if (lane == 0) accs[s] += r;
        }
    }
    if (lane == 0) {
#pragma unroll
        for (int s = 0; s < 4; s++) atomicAdd(wsum + s, accs[s]);
    }
}

__global__ void beta_kernel(const float* __restrict__ wsum, float* __restrict__ beta) {
    if (threadIdx.x == 0 && blockIdx.x == 0) {
        for (int h = 0; h < 2; h++) {
            float v[4], m = -1e30f;
            for (int s = 0; s < 4; s++) { v[s] = wsum[h * 4 + s] / (float)NN; if (v[s] > m) m = v[s]; }
            float sum = 0.f;
            for (int s = 0; s < 4; s++) { v[s] = expf(v[s] - m); sum += v[s]; }
            for (int s = 0; s < 4; s++) beta[h * 4 + s] = v[s] / sum;
        }
    }
}

__global__ void combine_kernel(const float* __restrict__ z0, const float* __restrict__ z1,
                               const float* __restrict__ z2, const float* __restrict__ z3,
                               const float* __restrict__ beta, float* __restrict__ out)
{
    int t = blockIdx.x * blockDim.x + threadIdx.x;
    if (t < NN * 16) {
        float b0 = __ldg(beta + 0), b1 = __ldg(beta + 1), b2 = __ldg(beta + 2), b3 = __ldg(beta + 3);
        float4 a = __ldg(reinterpret_cast<const float4*>(z0) + t);
        float4 b = __ldg(reinterpret_cast<const float4*>(z1) + t);
        float4 c = __ldg(reinterpret_cast<const float4*>(z2) + t);
        float4 d = __ldg(reinterpret_cast<const float4*>(z3) + t);
        float4 o;
        o.x = b0 * a.x + b1 * b.x + b2 * c.x + b3 * d.x;
        o.y = b0 * a.y + b1 * b.y + b2 * c.y + b3 * d.y;
        o.z = b0 * a.z + b1 * b.z + b2 * c.z + b3 * d.z;
        o.w = b0 * a.w + b1 * b.w + b2 * c.w + b3 * d.w;
        reinterpret_cast<float4*>(out)[t] = o;
    }
}

// ---------------- host launcher ----------------
extern "C" void kernel_launch(void* const* d_in, const int* in_sizes, int n_in,
                              void* d_out, int out_size)
{
    int xi[4], eii[4], hni[4], hli[4];
    int nx = 0, ne = 0, nh = 0, nl = 0;
    int iW1 = -1, ib1 = -1, iW2 = -1, ib2 = -1;
    int i8192[2]; int n8 = 0;
    int i128[4];  int n128 = 0;
    for (int i = 0; i < n_in; i++) {
        switch (in_sizes[i]) {
            case NN * FIN:   if (nx < 4) xi[nx++] = i; break;
            case 2 * EE:     if (ne < 4) eii[ne++] = i; break;
            case NN * 16:    if (nh < 4) hni[nh++] = i; break;
            case NN:         if (nl < 4) hli[nl++] = i; break;
            case FIN * DD1:  iW1 = i; break;
            case DD1:        ib1 = i; break;
            case DD1 * DD2:  iW2 = i; break;
            case DD2:        ib2 = i; break;
            case DD2 * HATT: if (n8 < 2) i8192[n8++] = i; break;
            case HATT:       if (n128 < 4) i128[n128++] = i; break;
            default: break;
        }
    }
    const float* X[4]; const int* EI[4];
    const int* HN[4]; const float* HL[4];
    for (int i = 0; i < 4; i++) {
        X[i]  = (const float*)d_in[xi[i]];
        EI[i] = (const int*)d_in[eii[i]];
        HN[i] = (const int*)d_in[hni[i]];
        HL[i] = (const float*)d_in[hli[i]];
    }
    const float* W1 = (const float*)d_in[iW1];
    const float* B1 = (const float*)d_in[ib1];
    const float* W2 = (const float*)d_in[iW2];
    const float* B2 = (const float*)d_in[ib2];
    const float* acW1 = (const float*)d_in[i8192[0]];
    const float* amW1 = (const float*)d_in[i8192[1]];
    const float* acB1 = (const float*)d_in[i128[0]];
    const float* acW2 = (const float*)d_in[i128[1]];
    const float* amB1 = (const float*)d_in[i128[2]];
    const float* amW2 = (const float*)d_in[i128[3]];

    float *E_, *ACC, *C1, *G, *X1, *X2, *DINV, *BINV, *WSUM, *BETA;
    int *WS, *STN, *STE, *ADJN, *ADJE;
    cudaGetSymbolAddress((void**)&E_,   g_E);
    cudaGetSymbolAddress((void**)&ACC,  g_acc);
    cudaGetSymbolAddress((void**)&C1,   g_C1);
    cudaGetSymbolAddress((void**)&G,    g_G);
    cudaGetSymbolAddress((void**)&X1,   g_x1);
    cudaGetSymbolAddress((void**)&X2,   g_x2);
    cudaGetSymbolAddress((void**)&DINV, g_dinv);
    cudaGetSymbolAddress((void**)&BINV, g_binv);
    cudaGetSymbolAddress((void**)&WSUM, g_wsum);
    cudaGetSymbolAddress((void**)&BETA, g_beta);
    cudaGetSymbolAddress((void**)&WS,   g_ws);
    cudaGetSymbolAddress((void**)&STN,  g_startn);
    cudaGetSymbolAddress((void**)&STE,  g_starte);
    cudaGetSymbolAddress((void**)&ADJN, g_adjn);
    cudaGetSymbolAddress((void**)&ADJE, g_adje);
    int* DEGN = WS;
    int* DEGE = WS + 4 * NN;
    int* CURN = WS + 8 * NN;
    int* CURE = WS + 12 * NN;
    int* CNT  = WS + 16 * NN;

    const size_t S = (size_t)NN * 64;
    const int TB = 256;
    auto gb = [](long n, int tb) { return (int)((n + tb - 1) / tb); };
    const int PROP_BLOCKS = gb((long)NG * NN * 32, TB);

    // ---- CSR build (all graphs) ----
    fill0_kernel<<<gb((16 * NN + 16) / 4, TB), TB>>>((float*)WS, (16 * NN + 16) / 4);
    deg_kernel<<<gb((long)NG * EE, TB), TB>>>(EI[0], EI[1], EI[2], EI[3], DEGN, DEGE);
    alloc_kernel<<<dim3(gb(NN, TB), NG), TB>>>(DEGN, DEGE, STN, STE, DINV, BINV, CNT);
    scatter_kernel<<<gb((long)NG * EE, TB), TB>>>(EI[0], EI[1], EI[2], EI[3],
                                                  STN, STE, CURN, CURE, ADJN, ADJE);

    // ---- conv1: propagate X (128 dims) through H, then tf32 GEMM (rowscale+bias+relu) ----
    seg_gather_kernel<128, true, false><<<PROP_BLOCKS, TB>>>(
        X[0], X[1], X[2], X[3], STE, DEGE, ADJE, BINV, nullptr, E_);
    {
        const float* e0 = E_;
        seg_gather_kernel<128, false, false><<<PROP_BLOCKS, TB>>>(
            e0, e0 + S * 2, e0 + S * 4, e0 + S * 6, STN, DEGN, ADJN, nullptr, nullptr, ACC);
    }
    mma_gemm_kernel<128, 2, 4, true><<<dim3(MP / 128, 2), TB>>>(ACC, W1, B1, DINV, C1, DD1, FIN);

    // ---- conv2: tf32 GEMM to 64 dims, then propagate with fused dinv+bias+relu ----
    mma_gemm_kernel<64, 4, 2, false><<<dim3(MP / 128, 1), TB>>>(C1, W2, nullptr, nullptr, G, DD2, DD1);
    seg_gather_kernel<64, true, false><<<PROP_BLOCKS, TB>>>(
        G, G + S, G + S * 2, G + S * 3, STE, DEGE, ADJE, BINV, nullptr, E_);
    {
        const float* e0 = E_;
        seg_gather_kernel<64, false, true><<<PROP_BLOCKS, TB>>>(
            e0, e0 + S, e0 + S * 2, e0 + S * 3, STN, DEGN, ADJN, DINV, B2, X1);
    }

    // ---- hyperedge embeddings (batched) ----
    hye_kernel<<<gb((long)NG * NN, 8), dim3(64, 8)>>>(
        X1, HN[0], HN[1], HN[2], HN[3], HL[0], HL[1], HL[2], HL[3], X2);

    // ---- fusion attention (both heads in one launch) ----
    fill0_kernel<<<1, TB>>>(WSUM, 2);
    attn_kernel<<<dim3(592, 2), TB>>>(
        X1 + 1 * S, X2 + 0 * S, X1 + 2 * S, X2 + 2 * S,
        X1 + 0 * S, X2 + 1 * S, X1 + 3 * S, X2 + 3 * S,
        acW1, acB1, acW2, amW1, amB1, amW2, WSUM);
    beta_kernel<<<1, 32>>>(WSUM, BETA);

    float* out = (float*)d_out;
    combine_kernel<<<gb((long)NN * 16, TB), TB>>>(X1 + 1 * S, X2 + 0 * S, X1 + 2 * S, X2 + 2 * S,
                                                  BETA, out);
    combine_kernel<<<gb((long)NN * 16, TB), TB>>>(X1 + 0 * S, X2 + 1 * S, X1 + 3 * S, X2 + 3 * S,
                                                  BETA + 4, out + S);
}

// round 9
// speedup vs baseline: 5.8414x; 1.5453x over previous
#include <cuda_runtime.h>
#include <math.h>
#include <stdint.h>

#define NN 50000
#define EE 800000
#define FIN 128
#define DD1 256
#define DD2 64
#define HATT 128
#define NG 4
#define MP 200064   // NG*NN padded to multiple of 128 (1563*128)
#define BKT 96      // adjacency bucket capacity (Poisson(16); P(deg>96) ~ 1e-50)

// ---------------- scratch (device globals; zero-initialized, no runtime alloc) ----
__device__ float g_E  [(size_t)NG * NN * 128];   // edge accumulator
__device__ float g_acc[(size_t)MP * 128];        // node accumulator (padded M)
__device__ float g_C1 [(size_t)MP * 256];        // conv1 output (padded M)
__device__ float g_G  [(size_t)MP * 64];         // conv2 GEMM out (padded M)
__device__ float g_x1 [(size_t)NG * NN * 64];
__device__ float g_x2 [(size_t)NG * NN * 64];
__device__ float g_dinv[MP];
__device__ float g_wsum[8];
__device__ float g_beta[8];
__device__ int   g_cnt2[2 * NG * NN];            // curn | cure
__device__ int   g_adjn[(size_t)NG * NN * BKT];  // edge ids grouped by node
__device__ int   g_adje[(size_t)NG * NN * BKT];  // node ids grouped by edge

// ---------------- small helpers ----------------
__device__ __forceinline__ unsigned f2tf(float f) {
    unsigned r; asm("cvt.rna.tf32.f32 %0, %1;" : "=r"(r) : "f"(f)); return r;
}
__device__ __forceinline__ void mma8(float& c0, float& c1, float& c2, float& c3,
                                     unsigned a0, unsigned a1, unsigned a2, unsigned a3,
                                     unsigned b0, unsigned b1) {
    asm volatile("mma.sync.aligned.m16n8k8.row.col.f32.tf32.tf32.f32 "
                 "{%0,%1,%2,%3}, {%4,%5,%6,%7}, {%8,%9}, {%0,%1,%2,%3};"
                 : "+f"(c0), "+f"(c1), "+f"(c2), "+f"(c3)
                 : "r"(a0), "r"(a1), "r"(a2), "r"(a3), "r"(b0), "r"(b1));
}
__device__ __forceinline__ void cpa16(void* dst_smem, const void* src) {
    unsigned d = (unsigned)__cvta_generic_to_shared(dst_smem);
    asm volatile("cp.async.ca.shared.global [%0], [%1], 16;" :: "r"(d), "l"(src));
}

// ---------------- utility kernels ----------------
__global__ void fill0_kernel(float* __restrict__ p, int n4) {
    int t = blockIdx.x * blockDim.x + threadIdx.x;
    if (t < n4) reinterpret_cast<float4*>(p)[t] = make_float4(0.f, 0.f, 0.f, 0.f);
}

// bucketed CSR build: counts + adjacency in one pass
__global__ void scatter_kernel(const int* e0, const int* e1, const int* e2, const int* e3,
                               int* __restrict__ curn, int* __restrict__ cure,
                               int* __restrict__ adjn, int* __restrict__ adje)
{
    int t = blockIdx.x * blockDim.x + threadIdx.x;
    if (t < NG * EE) {
        int g = t / EE, e = t - g * EE;
        const int* ei = (g == 0) ? e0 : (g == 1) ? e1 : (g == 2) ? e2 : e3;
        int v = __ldg(ei + e);
        int h = __ldg(ei + e + EE);
        int gv = g * NN + v, gh = g * NN + h;
        int q = atomicAdd(curn + gv, 1);
        if (q < BKT) adjn[(size_t)gv * BKT + q] = h;
        int p = atomicAdd(cure + gh, 1);
        if (p < BKT) adje[(size_t)gh * BKT + p] = v;
    }
}

__global__ void invert_kernel(const int* __restrict__ deg, float* __restrict__ dinv, int n) {
    int t = blockIdx.x * blockDim.x + threadIdx.x;
    if (t < n) { int d = __ldg(deg + t); dinv[t] = d > 0 ? (1.0f / (float)d) : 0.f; }
}

// segment-sum gather over batched rows, bucketed adjacency, inline 1/deg scaling.
// MODE 0: dst = (1/deg[row]) * sum        (edge pass)
// MODE 1: dst = sum                        (node pass, scale in GEMM epilogue)
// MODE 2: dst = relu((1/deg[row])*sum + bias[c])   (final node pass)
template<int DIM, int MODE>
__global__ __launch_bounds__(256) void seg_gather_kernel(
    const float* s0, const float* s1, const float* s2, const float* s3,
    const int* __restrict__ deg, const int* __restrict__ adj,
    const float* __restrict__ bias, float* __restrict__ dst)
{
    int row = (blockIdx.x * blockDim.x + threadIdx.x) >> 5;
    int lane = threadIdx.x & 31;
    if (row >= NG * NN) return;
    int g = row / NN;
    const float* src = (g == 0) ? s0 : (g == 1) ? s1 : (g == 2) ? s2 : s3;
    int du = __ldg(deg + row);
    int d = du < BKT ? du : BKT;
    const int* base = adj + (size_t)row * BKT;
    if (DIM == 128) {
        const float4* S = reinterpret_cast<const float4*>(src);
        float4 a = make_float4(0.f, 0.f, 0.f, 0.f);
        int k = 0;
        for (; k + 4 <= d; k += 4) {
            int j0 = __ldg(base + k + 0), j1 = __ldg(base + k + 1);
            int j2 = __ldg(base + k + 2), j3 = __ldg(base + k + 3);
            float4 v0 = __ldg(S + ((size_t)j0 << 5) + lane);
            float4 v1 = __ldg(S + ((size_t)j1 << 5) + lane);
            float4 v2 = __ldg(S + ((size_t)j2 << 5) + lane);
            float4 v3 = __ldg(S + ((size_t)j3 << 5) + lane);
            a.x += (v0.x + v1.x) + (v2.x + v3.x);
            a.y += (v0.y + v1.y) + (v2.y + v3.y);
            a.z += (v0.z + v1.z) + (v2.z + v3.z);
            a.w += (v0.w + v1.w) + (v2.w + v3.w);
        }
        for (; k < d; k++) {
            int j = __ldg(base + k);
            float4 v = __ldg(S + ((size_t)j << 5) + lane);
            a.x += v.x; a.y += v.y; a.z += v.z; a.w += v.w;
        }
        if (MODE == 0) {
            float b = du > 0 ? (1.0f / (float)du) : 0.f;
            a.x *= b; a.y *= b; a.z *= b; a.w *= b;
        }
        reinterpret_cast<float4*>(dst)[((size_t)row << 5) + lane] = a;
    } else {   // DIM == 64, two columns per lane
        const float2* S = reinterpret_cast<const float2*>(src);
        float2 a = make_float2(0.f, 0.f);
        int k = 0;
        for (; k + 4 <= d; k += 4) {
            int j0 = __ldg(base + k + 0), j1 = __ldg(base + k + 1);
            int j2 = __ldg(base + k + 2), j3 = __ldg(base + k + 3);
            float2 v0 = __ldg(S + ((size_t)j0 << 5) + lane);
            float2 v1 = __ldg(S + ((size_t)j1 << 5) + lane);
            float2 v2 = __ldg(S + ((size_t)j2 << 5) + lane);
            float2 v3 = __ldg(S + ((size_t)j3 << 5) + lane);
            a.x += (v0.x + v1.x) + (v2.x + v3.x);
            a.y += (v0.y + v1.y) + (v2.y + v3.y);
        }
        for (; k < d; k++) {
            int j = __ldg(base + k);
            float2 v = __ldg(S + ((size_t)j << 5) + lane);
            a.x += v.x; a.y += v.y;
        }
        if (MODE == 2) {
            float dv = du > 0 ? (1.0f / (float)du) : 0.f;
            float2 bb = __ldg(reinterpret_cast<const float2*>(bias) + lane);
            a.x = fmaxf(fmaf(dv, a.x, bb.x), 0.f);
            a.y = fmaxf(fmaf(dv, a.y, bb.y), 0.f);
        } else if (MODE == 0) {
            float b = du > 0 ? (1.0f / (float)du) : 0.f;
            a.x *= b; a.y *= b;
        }
        reinterpret_cast<float2*>(dst)[((size_t)row << 5) + lane] = a;
    }
}

// ---------------- tf32 tensor-core GEMM: C[M,Nn] = A[M,K] @ B[K,Nn] ----------------
template<int BN, int WR, int WC, bool EPI>
__global__ __launch_bounds__(256) void mma_gemm_kernel(
    const float* __restrict__ A, const float* __restrict__ Bm,
    const float* __restrict__ bias, const float* __restrict__ rs,
    float* __restrict__ C, int Nn, int K)
{
    const int BM = 128, BK = 32;
    const int WM = BM / WR, WN = BN / WC;
    const int MT = WM / 16, NT = WN / 8;
    __shared__ __align__(16) float As[BM][BK + 4];
    __shared__ __align__(16) float Bs[BK][BN + 4];
    int tid = threadIdx.x;
    int warp = tid >> 5, lane = tid & 31;
    int wm = (warp / WC) * WM;
    int wn = (warp % WC) * WN;
    size_t bm = (size_t)blockIdx.x * BM;
    int bn = blockIdx.y * BN;
    float acc[MT][NT][4] = {};

    for (int k0 = 0; k0 < K; k0 += BK) {
#pragma unroll
        for (int i = 0; i < 4; i++) {
            int c = tid + i * 256;
            int r = c >> 3, k4 = (c & 7) << 2;
            cpa16(&As[r][k4], A + (bm + r) * K + k0 + k4);
        }
#pragma unroll
        for (int i = 0; i < (BK * BN / 4) / 256; i++) {
            int c = tid + i * 256;
            int r = c / (BN / 4), n4 = (c % (BN / 4)) << 2;
            cpa16(&Bs[r][n4], Bm + (size_t)(k0 + r) * Nn + bn + n4);
        }
        asm volatile("cp.async.commit_group;");
        asm volatile("cp.async.wait_group 0;");
        __syncthreads();
#pragma unroll
        for (int ks = 0; ks < BK / 8; ks++) {
            unsigned af[MT][4], bf[NT][2];
            int kb = ks * 8 + (lane & 3);
            int rr = lane >> 2;
#pragma unroll
            for (int mt = 0; mt < MT; mt++) {
                int r = wm + mt * 16 + rr;
                af[mt][0] = f2tf(As[r][kb]);
                af[mt][1] = f2tf(As[r + 8][kb]);
                af[mt][2] = f2tf(As[r][kb + 4]);
                af[mt][3] = f2tf(As[r + 8][kb + 4]);
            }
#pragma unroll
            for (int nt = 0; nt < NT; nt++) {
                int n = wn + nt * 8 + rr;
                bf[nt][0] = f2tf(Bs[kb][n]);
                bf[nt][1] = f2tf(Bs[kb + 4][n]);
            }
#pragma unroll
            for (int mt = 0; mt < MT; mt++)
#pragma unroll
                for (int nt = 0; nt < NT; nt++)
                    mma8(acc[mt][nt][0], acc[mt][nt][1], acc[mt][nt][2], acc[mt][nt][3],
                         af[mt][0], af[mt][1], af[mt][2], af[mt][3],
                         bf[nt][0], bf[nt][1]);
        }
        __syncthreads();
    }
#pragma unroll
    for (int mt = 0; mt < MT; mt++) {
        size_t r0 = bm + wm + mt * 16 + (lane >> 2);
#pragma unroll
        for (int half = 0; half < 2; half++) {
            size_t r = r0 + half * 8;
            float sc = EPI ? __ldg(rs + r) : 1.0f;
#pragma unroll
            for (int nt = 0; nt < NT; nt++) {
                int col = bn + wn + nt * 8 + (lane & 3) * 2;
                float v0 = acc[mt][nt][half * 2 + 0];
                float v1 = acc[mt][nt][half * 2 + 1];
                if (EPI) {
                    v0 = fmaxf(fmaf(v0, sc, __ldg(bias + col)), 0.f);
                    v1 = fmaxf(fmaf(v1, sc, __ldg(bias + col + 1)), 0.f);
                }
                *reinterpret_cast<float2*>(C + r * Nn + col) = make_float2(v0, v1);
            }
        }
    }
}

// hyperedge embedding, batched over 4 graphs
__global__ void hye_kernel(const float* __restrict__ x1,
                           const int* h0, const int* h1, const int* h2, const int* h3,
                           const float* l0, const float* l1, const float* l2, const float* l3,
                           float* __restrict__ x2)
{
    int n = blockIdx.x * blockDim.y + threadIdx.y;
    if (n >= NG * NN) return;
    int g = n / NN, ln = n - g * NN;
    const int* hnode = (g == 0) ? h0 : (g == 1) ? h1 : (g == 2) ? h2 : h3;
    const float* hlen = (g == 0) ? l0 : (g == 1) ? l1 : (g == 2) ? l2 : l3;
    int c = threadIdx.x;   // 0..63
    const float* base = x1 + (size_t)g * NN * 64;
    float s = 0.f;
#pragma unroll
    for (int l = 0; l < 16; l++) {
        int j = __ldg(hnode + (size_t)ln * 16 + l);
        if (j > 0) s += __ldg(base + (size_t)(j - 1) * 64 + c);
    }
    x2[(size_t)n * 64 + c] = s / (__ldg(hlen + ln) + 1e-15f);
}

// ---------------- tensor-core fusion attention ----------------
// Logical A: M = 4*NN rows, row m = z_{m&3}[m>>2] (64 floats). H = A @ W1 (64->128).
// Epilogue: partial[s] += tanh(H + b1) . W2, block-reduced, atomicAdd to wsum.
__global__ __launch_bounds__(256) void attn_mma_kernel(
    const float* c0, const float* c1, const float* c2, const float* c3,
    const float* m0, const float* m1, const float* m2, const float* m3,
    const float* acW1, const float* acB1, const float* acW2,
    const float* amW1, const float* amB1, const float* amW2,
    float* __restrict__ wsum)
{
    const int BM = 128, BK = 32, BN = 128;
    const int WM = 64, WN = 32, MT = 4, NT = 4;   // 8 warps: 2 x 4
    __shared__ __align__(16) float As[BM][BK + 4];
    __shared__ __align__(16) float Bs[BK][BN + 8];
    __shared__ float sred[8][4];
    int head = blockIdx.y;
    const float* W1 = head ? amW1 : acW1;
    const float* b1 = head ? amB1 : acB1;
    const float* W2 = head ? amW2 : acW2;
    const float* zs[4];
    if (head == 0) { zs[0] = c0; zs[1] = c1; zs[2] = c2; zs[3] = c3; }
    else           { zs[0] = m0; zs[1] = m1; zs[2] = m2; zs[3] = m3; }

    int tid = threadIdx.x;
    int warp = tid >> 5, lane = tid & 31;
    int q = lane & 3, rr = lane >> 2;
    int wm = (warp >> 2) * WM;       // warp/4 in {0,1}
    int wn = (warp & 3) * WN;
    size_t bm = (size_t)blockIdx.x * BM;
    float acc[MT][NT][4] = {};

    for (int k0 = 0; k0 < 64; k0 += BK) {
        // A tile: 128 rows x 32 floats; row pointers computed from (m&3, m>>2)
#pragma unroll
        for (int i = 0; i < 4; i++) {
            int c = tid + i * 256;
            int r = c >> 3, k4 = (c & 7) << 2;
            size_t m = bm + r;
            const float* p = (m < (size_t)4 * NN) ? zs[m & 3] + (m >> 2) * 64 : zs[0];
            cpa16(&As[r][k4], p + k0 + k4);
        }
        // B tile: W1 rows k0..k0+31, 128 cols
#pragma unroll
        for (int i = 0; i < 4; i++) {
            int c = tid + i * 256;
            int r = c >> 5, n4 = (c & 31) << 2;
            cpa16(&Bs[r][n4], W1 + (size_t)(k0 + r) * 128 + n4);
        }
        asm volatile("cp.async.commit_group;");
        asm volatile("cp.async.wait_group 0;");
        __syncthreads();
#pragma unroll
        for (int ks = 0; ks < BK / 8; ks++) {
            unsigned af[MT][4], bf[NT][2];
            int kb = ks * 8 + q;
#pragma unroll
            for (int mt = 0; mt < MT; mt++) {
                int r = wm + mt * 16 + rr;
                af[mt][0] = f2tf(As[r][kb]);
                af[mt][1] = f2tf(As[r + 8][kb]);
                af[mt][2] = f2tf(As[r][kb + 4]);
                af[mt][3] = f2tf(As[r + 8][kb + 4]);
            }
#pragma unroll
            for (int nt = 0; nt < NT; nt++) {
                int n = wn + nt * 8 + rr;
                bf[nt][0] = f2tf(Bs[kb][n]);
                bf[nt][1] = f2tf(Bs[kb + 4][n]);
            }
#pragma unroll
            for (int mt = 0; mt < MT; mt++)
#pragma unroll
                for (int nt = 0; nt < NT; nt++)
                    mma8(acc[mt][nt][0], acc[mt][nt][1], acc[mt][nt][2], acc[mt][nt][3],
                         af[mt][0], af[mt][1], af[mt][2], af[mt][3],
                         bf[nt][0], bf[nt][1]);
        }
        __syncthreads();
    }
    // epilogue: tanh + dot W2, accumulate per slot s = row & 3 = rr & 3 (constant per thread)
    float part = 0.f;
#pragma unroll
    for (int mt = 0; mt < MT; mt++) {
#pragma unroll
        for (int half = 0; half < 2; half++) {
            size_t m = bm + wm + mt * 16 + rr + half * 8;
            bool valid = m < (size_t)4 * NN;
            float v = 0.f;
#pragma unroll
            for (int nt = 0; nt < NT; nt++) {
                int col = wn + nt * 8 + q * 2;
                float h0 = acc[mt][nt][half * 2 + 0] + __ldg(b1 + col);
                float h1 = acc[mt][nt][half * 2 + 1] + __ldg(b1 + col + 1);
                v += tanhf(h0) * __ldg(W2 + col) + tanhf(h1) * __ldg(W2 + col + 1);
            }
            if (valid) part += v;
        }
    }
    // lanes sharing s: xor 1, 2, 16
    part += __shfl_xor_sync(0xffffffffu, part, 1);
    part += __shfl_xor_sync(0xffffffffu, part, 2);
    part += __shfl_xor_sync(0xffffffffu, part, 16);
    if (q == 0 && rr < 4) sred[warp][rr] = part;   // rr = s for lanes 0,4,8,12
    __syncthreads();
    if (tid < 4) {
        float s = 0.f;
#pragma unroll
        for (int w = 0; w < 8; w++) s += sred[w][tid];
        atomicAdd(wsum + head * 4 + tid, s);
    }
}

__global__ void beta_kernel(const float* __restrict__ wsum, float* __restrict__ beta) {
    if (threadIdx.x == 0 && blockIdx.x == 0) {
        for (int h = 0; h < 2; h++) {
            float v[4], m = -1e30f;
            for (int s = 0; s < 4; s++) { v[s] = wsum[h * 4 + s] / (float)NN; if (v[s] > m) m = v[s]; }
            float sum = 0.f;
            for (int s = 0; s < 4; s++) { v[s] = expf(v[s] - m); sum += v[s]; }
            for (int s = 0; s < 4; s++) beta[h * 4 + s] = v[s] / sum;
        }
    }
}

// both heads: grid.y selects pointer set + beta row + output half
__global__ void combine_kernel(const float* c0, const float* c1, const float* c2, const float* c3,
                               const float* m0, const float* m1, const float* m2, const float* m3,
                               const float* __restrict__ beta, float* __restrict__ out)
{
    int t = blockIdx.x * blockDim.x + threadIdx.x;
    int head = blockIdx.y;
    if (t < NN * 16) {
        const float* z0 = head ? m0 : c0; const float* z1 = head ? m1 : c1;
        const float* z2 = head ? m2 : c2; const float* z3 = head ? m3 : c3;
        const float* be = beta + head * 4;
        float b0 = __ldg(be + 0), b1 = __ldg(be + 1), b2 = __ldg(be + 2), b3 = __ldg(be + 3);
        float4 a = __ldg(reinterpret_cast<const float4*>(z0) + t);
        float4 b = __ldg(reinterpret_cast<const float4*>(z1) + t);
        float4 c = __ldg(reinterpret_cast<const float4*>(z2) + t);
        float4 d = __ldg(reinterpret_cast<const float4*>(z3) + t);
        float4 o;
        o.x = b0 * a.x + b1 * b.x + b2 * c.x + b3 * d.x;
        o.y = b0 * a.y + b1 * b.y + b2 * c.y + b3 * d.y;
        o.z = b0 * a.z + b1 * b.z + b2 * c.z + b3 * d.z;
        o.w = b0 * a.w + b1 * b.w + b2 * c.w + b3 * d.w;
        reinterpret_cast<float4*>(out + (size_t)head * NN * 64)[t] = o;
    }
}

// ---------------- host launcher ----------------
extern "C" void kernel_launch(void* const* d_in, const int* in_sizes, int n_in,
                              void* d_out, int out_size)
{
    int xi[4], eii[4], hni[4], hli[4];
    int nx = 0, ne = 0, nh = 0, nl = 0;
    int iW1 = -1, ib1 = -1, iW2 = -1, ib2 = -1;
    int i8192[2]; int n8 = 0;
    int i128[4];  int n128 = 0;
    for (int i = 0; i < n_in; i++) {
        switch (in_sizes[i]) {
            case NN * FIN:   if (nx < 4) xi[nx++] = i; break;
            case 2 * EE:     if (ne < 4) eii[ne++] = i; break;
            case NN * 16:    if (nh < 4) hni[nh++] = i; break;
            case NN:         if (nl < 4) hli[nl++] = i; break;
            case FIN * DD1:  iW1 = i; break;
            case DD1:        ib1 = i; break;
            case DD1 * DD2:  iW2 = i; break;
            case DD2:        ib2 = i; break;
            case DD2 * HATT: if (n8 < 2) i8192[n8++] = i; break;
            case HATT:       if (n128 < 4) i128[n128++] = i; break;
            default: break;
        }
    }
    const float* X[4]; const int* EI[4];
    const int* HN[4]; const float* HL[4];
    for (int i = 0; i < 4; i++) {
        X[i]  = (const float*)d_in[xi[i]];
        EI[i] = (const int*)d_in[eii[i]];
        HN[i] = (const int*)d_in[hni[i]];
        HL[i] = (const float*)d_in[hli[i]];
    }
    const float* W1 = (const float*)d_in[iW1];
    const float* B1 = (const float*)d_in[ib1];
    const float* W2 = (const float*)d_in[iW2];
    const float* B2 = (const float*)d_in[ib2];
    const float* acW1 = (const float*)d_in[i8192[0]];
    const float* amW1 = (const float*)d_in[i8192[1]];
    const float* acB1 = (const float*)d_in[i128[0]];
    const float* acW2 = (const float*)d_in[i128[1]];
    const float* amB1 = (const float*)d_in[i128[2]];
    const float* amW2 = (const float*)d_in[i128[3]];

    float *E_, *ACC, *C1, *G, *X1, *X2, *DINV, *WSUM, *BETA;
    int *CNT2, *ADJN, *ADJE;
    cudaGetSymbolAddress((void**)&E_,   g_E);
    cudaGetSymbolAddress((void**)&ACC,  g_acc);
    cudaGetSymbolAddress((void**)&C1,   g_C1);
    cudaGetSymbolAddress((void**)&G,    g_G);
    cudaGetSymbolAddress((void**)&X1,   g_x1);
    cudaGetSymbolAddress((void**)&X2,   g_x2);
    cudaGetSymbolAddress((void**)&DINV, g_dinv);
    cudaGetSymbolAddress((void**)&WSUM, g_wsum);
    cudaGetSymbolAddress((void**)&BETA, g_beta);
    cudaGetSymbolAddress((void**)&CNT2, g_cnt2);
    cudaGetSymbolAddress((void**)&ADJN, g_adjn);
    cudaGetSymbolAddress((void**)&ADJE, g_adje);
    int* CURN = CNT2;
    int* CURE = CNT2 + NG * NN;

    const size_t S = (size_t)NN * 64;
    const int TB = 256;
    auto gb = [](long n, int tb) { return (int)((n + tb - 1) / tb); };
    const int PROP_BLOCKS = gb((long)NG * NN * 32, TB);

    // ---- bucketed CSR build (all graphs, one pass) ----
    fill0_kernel<<<gb((2 * NG * NN) / 4, TB), TB>>>((float*)CNT2, (2 * NG * NN) / 4);
    fill0_kernel<<<1, 32>>>(WSUM, 2);
    scatter_kernel<<<gb((long)NG * EE, TB), TB>>>(EI[0], EI[1], EI[2], EI[3],
                                                  CURN, CURE, ADJN, ADJE);
    invert_kernel<<<gb(NG * NN, TB), TB>>>(CURN, DINV, NG * NN);

    // ---- conv1: propagate X (128 dims), then tf32 GEMM (dinv+bias+relu) ----
    seg_gather_kernel<128, 0><<<PROP_BLOCKS, TB>>>(
        X[0], X[1], X[2], X[3], CURE, ADJE, nullptr, E_);
    {
        const float* e0 = E_;
        seg_gather_kernel<128, 1><<<PROP_BLOCKS, TB>>>(
            e0, e0 + S * 2, e0 + S * 4, e0 + S * 6, CURN, ADJN, nullptr, ACC);
    }
    mma_gemm_kernel<128, 2, 4, true><<<dim3(MP / 128, 2), TB>>>(ACC, W1, B1, DINV, C1, DD1, FIN);

    // ---- conv2: tf32 GEMM to 64 dims, then propagate with fused 1/deg+bias+relu ----
    mma_gemm_kernel<64, 4, 2, false><<<dim3(MP / 128, 1), TB>>>(C1, W2, nullptr, nullptr, G, DD2, DD1);
    seg_gather_kernel<64, 0><<<PROP_BLOCKS, TB>>>(
        G, G + S, G + S * 2, G + S * 3, CURE, ADJE, nullptr, E_);
    {
        const float* e0 = E_;
        seg_gather_kernel<64, 2><<<PROP_BLOCKS, TB>>>(
            e0, e0 + S, e0 + S * 2, e0 + S * 3, CURN, ADJN, B2, X1);
    }

    // ---- hyperedge embeddings (batched) ----
    hye_kernel<<<gb((long)NG * NN, 8), dim3(64, 8)>>>(
        X1, HN[0], HN[1], HN[2], HN[3], HL[0], HL[1], HL[2], HL[3], X2);

    // ---- fusion attention via tensor cores (both heads) ----
    attn_mma_kernel<<<dim3((4 * NN + 127) / 128, 2), TB>>>(
        X1 + 1 * S, X2 + 0 * S, X1 + 2 * S, X2 + 2 * S,
        X1 + 0 * S, X2 + 1 * S, X1 + 3 * S, X2 + 3 * S,
        acW1, acB1, acW2, amW1, amB1, amW2, WSUM);
    beta_kernel<<<1, 32>>>(WSUM, BETA);

    float* out = (float*)d_out;
    combine_kernel<<<dim3(gb((long)NN * 16, TB), 2), TB>>>(
        X1 + 1 * S, X2 + 0 * S, X1 + 2 * S, X2 + 2 * S,
        X1 + 0 * S, X2 + 1 * S, X1 + 3 * S, X2 + 3 * S,
        BETA, out);
}